// round 1
// baseline (speedup 1.0000x reference)
#include <cuda_runtime.h>
#include <math.h>

// Problem constants
#define NB     32768
#define DMODEL 512
#define NH     8
#define DHEAD  64

// ---------------------------------------------------------------------------
// Scratch: 6 projection buffers (attention outputs are written back over
// q1/q2 in-place, per-warp-per-sample safe). 6 * 64MB = 384MB static device.
// ---------------------------------------------------------------------------
__device__ float g_q1[(size_t)NB * DMODEL];
__device__ float g_k1[(size_t)NB * DMODEL];
__device__ float g_v1[(size_t)NB * DMODEL];
__device__ float g_q2[(size_t)NB * DMODEL];
__device__ float g_k2[(size_t)NB * DMODEL];
__device__ float g_v2[(size_t)NB * DMODEL];

// ---------------------------------------------------------------------------
// Batched SGEMM + bias:  C[z] = X[z] @ W[z]^T + bias[z]
//   X: [M, 512] row-major, W: [512, 512] row-major (K contiguous in both).
//   BM=BN=128, BK=16, 256 threads, 8x8 microtile per thread.
// ---------------------------------------------------------------------------
struct GemmBatch {
    const float* X[6];
    const float* W[6];
    const float* bias[6];
    float*       C[6];
};

__global__ __launch_bounds__(256, 2)
void gemm_bias_kernel(GemmBatch args)
{
    const int z = blockIdx.z;
    const float* __restrict__ X    = args.X[z];
    const float* __restrict__ W    = args.W[z];
    const float* __restrict__ bias = args.bias[z];
    float* __restrict__       C    = args.C[z];

    __shared__ float As[16][128];   // As[k][m]
    __shared__ float Bs[16][128];   // Bs[k][n]

    const int tid = threadIdx.x;
    const int tx  = tid & 15;       // 0..15  -> n microtile
    const int ty  = tid >> 4;       // 0..15  -> m microtile
    const int m0  = blockIdx.y * 128;
    const int n0  = blockIdx.x * 128;

    // loader mapping: 256 threads, each loads one float4 per 64-row half
    const int lrow = tid >> 2;          // 0..63
    const int lk   = (tid & 3) << 2;    // 0,4,8,12

    float acc[8][8];
#pragma unroll
    for (int i = 0; i < 8; ++i)
#pragma unroll
        for (int j = 0; j < 8; ++j)
            acc[i][j] = 0.f;

    for (int kt = 0; kt < DMODEL; kt += 16) {
#pragma unroll
        for (int r = 0; r < 2; ++r) {
            const int row = lrow + r * 64;
            float4 xa = *(const float4*)(X + (size_t)(m0 + row) * DMODEL + kt + lk);
            As[lk + 0][row] = xa.x;
            As[lk + 1][row] = xa.y;
            As[lk + 2][row] = xa.z;
            As[lk + 3][row] = xa.w;
            float4 wa = *(const float4*)(W + (size_t)(n0 + row) * DMODEL + kt + lk);
            Bs[lk + 0][row] = wa.x;
            Bs[lk + 1][row] = wa.y;
            Bs[lk + 2][row] = wa.z;
            Bs[lk + 3][row] = wa.w;
        }
        __syncthreads();

#pragma unroll
        for (int k = 0; k < 16; ++k) {
            float a[8], b[8];
            *(float4*)&a[0] = *(const float4*)&As[k][ty * 8];
            *(float4*)&a[4] = *(const float4*)&As[k][ty * 8 + 4];
            *(float4*)&b[0] = *(const float4*)&Bs[k][tx * 8];
            *(float4*)&b[4] = *(const float4*)&Bs[k][tx * 8 + 4];
#pragma unroll
            for (int i = 0; i < 8; ++i)
#pragma unroll
                for (int j = 0; j < 8; ++j)
                    acc[i][j] = fmaf(a[i], b[j], acc[i][j]);
        }
        __syncthreads();
    }

    // epilogue: add bias, vectorized stores
    float bvec[8];
#pragma unroll
    for (int j = 0; j < 8; ++j)
        bvec[j] = bias[n0 + tx * 8 + j];

#pragma unroll
    for (int i = 0; i < 8; ++i) {
        float4 o0, o1;
        o0.x = acc[i][0] + bvec[0];
        o0.y = acc[i][1] + bvec[1];
        o0.z = acc[i][2] + bvec[2];
        o0.w = acc[i][3] + bvec[3];
        o1.x = acc[i][4] + bvec[4];
        o1.y = acc[i][5] + bvec[5];
        o1.z = acc[i][6] + bvec[6];
        o1.w = acc[i][7] + bvec[7];
        float* cp = C + (size_t)(m0 + ty * 8 + i) * DMODEL + n0 + tx * 8;
        *(float4*)cp       = o0;
        *(float4*)(cp + 4) = o1;
    }
}

// ---------------------------------------------------------------------------
// Per-sample head-mixing attention. One warp handles one sample, both sides.
//   scores[h][e] = q[h] . k[e] / 8 ; softmax over e ; out[h] = sum_e a[h][e] v[e]
// Writes o1 over q1 buffer, o2 over q2 buffer (reads staged to smem first).
// ---------------------------------------------------------------------------
__global__ __launch_bounds__(128)
void attention_kernel(const float* __restrict__ q1, const float* __restrict__ k1,
                      const float* __restrict__ v1, const float* __restrict__ q2,
                      const float* __restrict__ k2, const float* __restrict__ v2,
                      float* __restrict__ o1, float* __restrict__ o2)
{
    __shared__ float sq[4][NH][68];   // pad 68 -> conflict-free strided reads
    __shared__ float sk[4][NH][68];
    __shared__ float sv[4][NH][68];
    __shared__ float ss[4][NH][NH];

    const int w = threadIdx.x >> 5;
    const int l = threadIdx.x & 31;
    const int s = blockIdx.x * 4 + w;

    const float* Q[2] = { q1 + (size_t)s * DMODEL, q2 + (size_t)s * DMODEL };
    const float* K[2] = { k1 + (size_t)s * DMODEL, k2 + (size_t)s * DMODEL };
    const float* V[2] = { v1 + (size_t)s * DMODEL, v2 + (size_t)s * DMODEL };
    float*       O[2] = { o1 + (size_t)s * DMODEL, o2 + (size_t)s * DMODEL };

    for (int side = 0; side < 2; ++side) {
        const float* q = Q[side];
        const float* k = K[side];
        const float* v = V[side];

        // stage q,k,v into smem (coalesced global reads)
#pragma unroll
        for (int i = 0; i < 16; ++i) {
            const int idx = i * 32 + l;
            const int h = idx >> 6, d = idx & 63;
            sq[w][h][d] = q[idx];
            sk[w][h][d] = k[idx];
            sv[w][h][d] = v[idx];
        }
        __syncwarp();

        // scores: each lane does 2 of the 64 (h,e) dot products
#pragma unroll
        for (int pp = 0; pp < 2; ++pp) {
            const int p = l + pp * 32;
            const int h = p >> 3, e = p & 7;
            float acc = 0.f;
#pragma unroll
            for (int d = 0; d < DHEAD; ++d)
                acc = fmaf(sq[w][h][d], sk[w][e][d], acc);
            ss[w][h][e] = acc * 0.125f;   // / sqrt(64)
        }
        __syncwarp();

        // softmax over e, one lane per head
        if (l < NH) {
            float m = -1e30f;
#pragma unroll
            for (int e = 0; e < NH; ++e) m = fmaxf(m, ss[w][l][e]);
            float ex[NH];
            float sum = 0.f;
#pragma unroll
            for (int e = 0; e < NH; ++e) { ex[e] = expf(ss[w][l][e] - m); sum += ex[e]; }
            const float inv = 1.f / sum;
#pragma unroll
            for (int e = 0; e < NH; ++e) ss[w][l][e] = ex[e] * inv;
        }
        __syncwarp();

        // out[h][d] = sum_e attn[h][e] * v[e][d]; lanes cover d = l, l+32
#pragma unroll
        for (int dd = 0; dd < 2; ++dd) {
            const int d = l + dd * 32;
#pragma unroll
            for (int h = 0; h < NH; ++h) {
                float acc = 0.f;
#pragma unroll
                for (int e = 0; e < NH; ++e)
                    acc = fmaf(ss[w][h][e], sv[w][e][d], acc);
                O[side][h * DHEAD + d] = acc;
            }
        }
        __syncwarp();
    }
}

// ---------------------------------------------------------------------------
// kernel_launch
// ---------------------------------------------------------------------------
extern "C" void kernel_launch(void* const* d_in, const int* in_sizes, int n_in,
                              void* d_out, int out_size)
{
    const float* prot = (const float*)d_in[0];
    const float* lig  = (const float*)d_in[1];
    const float* Wq1 = (const float*)d_in[2];  const float* bq1 = (const float*)d_in[3];
    const float* Wk1 = (const float*)d_in[4];  const float* bk1 = (const float*)d_in[5];
    const float* Wv1 = (const float*)d_in[6];  const float* bv1 = (const float*)d_in[7];
    const float* Wq2 = (const float*)d_in[8];  const float* bq2 = (const float*)d_in[9];
    const float* Wk2 = (const float*)d_in[10]; const float* bk2 = (const float*)d_in[11];
    const float* Wv2 = (const float*)d_in[12]; const float* bv2 = (const float*)d_in[13];
    const float* Wo1 = (const float*)d_in[14]; const float* bo1 = (const float*)d_in[15];
    const float* Wo2 = (const float*)d_in[16]; const float* bo2 = (const float*)d_in[17];

    float* out      = (float*)d_out;
    float* prot_out = out;
    float* lig_out  = out + (size_t)NB * DMODEL;

    float *q1, *k1, *v1, *q2, *k2, *v2;
    cudaGetSymbolAddress((void**)&q1, g_q1);
    cudaGetSymbolAddress((void**)&k1, g_k1);
    cudaGetSymbolAddress((void**)&v1, g_v1);
    cudaGetSymbolAddress((void**)&q2, g_q2);
    cudaGetSymbolAddress((void**)&k2, g_k2);
    cudaGetSymbolAddress((void**)&v2, g_v2);

    // 6 fused input projections: q1(P), k1(L), v1(L), q2(L), k2(P), v2(P)
    GemmBatch pj;
    pj.X[0] = prot; pj.W[0] = Wq1; pj.bias[0] = bq1; pj.C[0] = q1;
    pj.X[1] = lig;  pj.W[1] = Wk1; pj.bias[1] = bk1; pj.C[1] = k1;
    pj.X[2] = lig;  pj.W[2] = Wv1; pj.bias[2] = bv1; pj.C[2] = v1;
    pj.X[3] = lig;  pj.W[3] = Wq2; pj.bias[3] = bq2; pj.C[3] = q2;
    pj.X[4] = prot; pj.W[4] = Wk2; pj.bias[4] = bk2; pj.C[4] = k2;
    pj.X[5] = prot; pj.W[5] = Wv2; pj.bias[5] = bv2; pj.C[5] = v2;

    dim3 gproj(DMODEL / 128, NB / 128, 6);
    gemm_bias_kernel<<<gproj, 256>>>(pj);

    // attention: o1 -> q1 buffer, o2 -> q2 buffer (in-place safe)
    attention_kernel<<<NB / 4, 128>>>(q1, k1, v1, q2, k2, v2, q1, q2);

    // output projections straight into d_out
    GemmBatch op;
    op.X[0] = q1; op.W[0] = Wo1; op.bias[0] = bo1; op.C[0] = prot_out;
    op.X[1] = q2; op.W[1] = Wo2; op.bias[1] = bo2; op.C[1] = lig_out;
    // unused slots (grid.z = 2 never reads them)
    for (int i = 2; i < 6; ++i) { op.X[i] = q1; op.W[i] = Wo1; op.bias[i] = bo1; op.C[i] = prot_out; }

    dim3 gout(DMODEL / 128, NB / 128, 2);
    gemm_bias_kernel<<<gout, 256>>>(op);
}

// round 4
// speedup vs baseline: 1.7973x; 1.7973x over previous
#include <cuda_runtime.h>
#include <cuda_fp16.h>
#include <cstdint>
#include <math.h>

#define NB     32768
#define DMODEL 512
#define NHEADS 8
#define DHEAD  64

// GEMM tiling
#define BM 256
#define BN 128
#define BK 32                     // halves of K per stage
#define PADH 40                   // smem row stride in halves (80B) - conflict-free

// ---------------------------------------------------------------------------
// Scratch buffers
// ---------------------------------------------------------------------------
__device__ float g_q1[(size_t)NB * DMODEL];
__device__ float g_k1[(size_t)NB * DMODEL];
__device__ float g_v1[(size_t)NB * DMODEL];
__device__ float g_q2[(size_t)NB * DMODEL];
__device__ float g_k2[(size_t)NB * DMODEL];
__device__ float g_v2[(size_t)NB * DMODEL];

// fp16 hi/lo split copies
__device__ __half g_prot_h[(size_t)NB * DMODEL];
__device__ __half g_prot_l[(size_t)NB * DMODEL];
__device__ __half g_lig_h [(size_t)NB * DMODEL];
__device__ __half g_lig_l [(size_t)NB * DMODEL];
__device__ __half g_o1_h  [(size_t)NB * DMODEL];
__device__ __half g_o1_l  [(size_t)NB * DMODEL];
__device__ __half g_o2_h  [(size_t)NB * DMODEL];
__device__ __half g_o2_l  [(size_t)NB * DMODEL];
__device__ __half g_W_h[8][DMODEL * DMODEL];
__device__ __half g_W_l[8][DMODEL * DMODEL];

// ---------------------------------------------------------------------------
// helpers
// ---------------------------------------------------------------------------
__device__ __forceinline__ uint32_t smem_u32(const void* p) {
    uint32_t a;
    asm("{ .reg .u64 t; cvta.to.shared.u64 t, %1; cvt.u32.u64 %0, t; }"
        : "=r"(a) : "l"(p));
    return a;
}
__device__ __forceinline__ void cp16(uint32_t dst, const void* src) {
    asm volatile("cp.async.cg.shared.global [%0], [%1], 16;" :: "r"(dst), "l"(src));
}
#define CP_COMMIT() asm volatile("cp.async.commit_group;" ::: "memory")
template <int N> __device__ __forceinline__ void cp_wait() {
    asm volatile("cp.async.wait_group %0;" :: "n"(N) : "memory");
}

// m16n8k16 fp16 MMA, fp32 accumulate (sm_80+, legal in base compute_103 PTX)
__device__ __forceinline__ void mma_f16(float* d, const uint32_t* a, const uint32_t* b) {
    asm volatile(
        "mma.sync.aligned.m16n8k16.row.col.f32.f16.f16.f32 "
        "{%0,%1,%2,%3}, {%4,%5,%6,%7}, {%8,%9}, {%0,%1,%2,%3};"
        : "+f"(d[0]), "+f"(d[1]), "+f"(d[2]), "+f"(d[3])
        : "r"(a[0]), "r"(a[1]), "r"(a[2]), "r"(a[3]), "r"(b[0]), "r"(b[1]));
}

// ---------------------------------------------------------------------------
// fp32 -> (hi fp16, lo fp16) split kernels
// ---------------------------------------------------------------------------
__global__ __launch_bounds__(256)
void split_kernel(const float2* __restrict__ src, __half2* __restrict__ hi,
                  __half2* __restrict__ lo, int n2)
{
    for (int i = blockIdx.x * blockDim.x + threadIdx.x; i < n2;
         i += gridDim.x * blockDim.x) {
        float2 v = src[i];
        __half2 h = __floats2half2_rn(v.x, v.y);
        float2 hb = __half22float2(h);
        __half2 l = __floats2half2_rn(v.x - hb.x, v.y - hb.y);
        hi[i] = h;
        lo[i] = l;
    }
}

struct WSplit { const float* src[8]; };

__global__ __launch_bounds__(256)
void split_w_kernel(WSplit ws)
{
    const int z = blockIdx.y;
    const float2* src = (const float2*)ws.src[z];
    __half2* hi = (__half2*)&g_W_h[z][0];
    __half2* lo = (__half2*)&g_W_l[z][0];
    const int n2 = DMODEL * DMODEL / 2;
    for (int i = blockIdx.x * blockDim.x + threadIdx.x; i < n2;
         i += gridDim.x * blockDim.x) {
        float2 v = src[i];
        __half2 h = __floats2half2_rn(v.x, v.y);
        float2 hb = __half22float2(h);
        __half2 l = __floats2half2_rn(v.x - hb.x, v.y - hb.y);
        hi[i] = h;
        lo[i] = l;
    }
}

// ---------------------------------------------------------------------------
// split-fp16 tensor-core GEMM: C = X @ W^T + bias  (fp32-accuracy via 3 MMAs)
//   CTA tile 256x128, BK=32 halves/stage, 256 threads (8 warps), warp 64x64.
// ---------------------------------------------------------------------------
struct GemmBatch {
    const __half* Xh[6];
    const __half* Xl[6];
    const __half* Wh[6];
    const __half* Wl[6];
    const float*  bias[6];
    float*        C[6];
};

#define STAGE_HALVES ((BM + BM + BN + BN) * PADH)   // 30720 halves = 61440 B

__global__ __launch_bounds__(256, 1)
void gemm_mma_kernel(GemmBatch args)
{
    const int z = blockIdx.z;
    const __half* __restrict__ Xh = args.Xh[z];
    const __half* __restrict__ Xl = args.Xl[z];
    const __half* __restrict__ Wh = args.Wh[z];
    const __half* __restrict__ Wl = args.Wl[z];
    const float*  __restrict__ bias = args.bias[z];
    float*        __restrict__ C    = args.C[z];

    const int n0 = blockIdx.x * BN;     // n fastest -> A stripe reused by 4 CTAs
    const int m0 = blockIdx.y * BM;

    extern __shared__ __half hsm[];
    // per stage: Ah[BM][PADH], Al[BM][PADH], Bh[BN][PADH], Bl[BN][PADH]
    __half* pAh[2]; __half* pAl[2]; __half* pBh[2]; __half* pBl[2];
#pragma unroll
    for (int s = 0; s < 2; ++s) {
        __half* base = hsm + s * STAGE_HALVES;
        pAh[s] = base;
        pAl[s] = base + BM * PADH;
        pBh[s] = base + 2 * BM * PADH;
        pBl[s] = base + 2 * BM * PADH + BN * PADH;
    }
    uint32_t aAh[2], aAl[2], aBh[2], aBl[2];
#pragma unroll
    for (int s = 0; s < 2; ++s) {
        aAh[s] = smem_u32(pAh[s]);
        aAl[s] = smem_u32(pAl[s]);
        aBh[s] = smem_u32(pBh[s]);
        aBl[s] = smem_u32(pBl[s]);
    }

    const int tid  = threadIdx.x;
    const int wid  = tid >> 5;
    const int lane = tid & 31;
    const int r  = lane >> 2;
    const int cq = lane & 3;

    const int wm = (wid >> 1) * 64;
    const int wn = (wid & 1) * 64;

    float acc[4][8][4];
#pragma unroll
    for (int i = 0; i < 4; ++i)
#pragma unroll
        for (int j = 0; j < 8; ++j)
#pragma unroll
            for (int k = 0; k < 4; ++k)
                acc[i][j][k] = 0.f;

    // loader: A tiles 256 rows x 32 halves (64B) = 4 chunks/row
#define LOAD_STAGE(kt, s) do {                                                   \
        const size_t koff = (size_t)(kt) * BK;                                    \
        _Pragma("unroll")                                                        \
        for (int i = 0; i < 4; ++i) {                                            \
            int idx = tid + i * 256; int row = idx >> 2; int ch = idx & 3;       \
            cp16(aAh[s] + row * (PADH * 2) + ch * 16,                            \
                 Xh + (size_t)(m0 + row) * DMODEL + koff + ch * 8);              \
        }                                                                        \
        _Pragma("unroll")                                                        \
        for (int i = 0; i < 4; ++i) {                                            \
            int idx = tid + i * 256; int row = idx >> 2; int ch = idx & 3;       \
            cp16(aAl[s] + row * (PADH * 2) + ch * 16,                            \
                 Xl + (size_t)(m0 + row) * DMODEL + koff + ch * 8);              \
        }                                                                        \
        _Pragma("unroll")                                                        \
        for (int i = 0; i < 2; ++i) {                                            \
            int idx = tid + i * 256; int row = idx >> 2; int ch = idx & 3;       \
            cp16(aBh[s] + row * (PADH * 2) + ch * 16,                            \
                 Wh + (size_t)(n0 + row) * DMODEL + koff + ch * 8);              \
        }                                                                        \
        _Pragma("unroll")                                                        \
        for (int i = 0; i < 2; ++i) {                                            \
            int idx = tid + i * 256; int row = idx >> 2; int ch = idx & 3;       \
            cp16(aBl[s] + row * (PADH * 2) + ch * 16,                            \
                 Wl + (size_t)(n0 + row) * DMODEL + koff + ch * 8);              \
        }                                                                        \
        CP_COMMIT();                                                             \
    } while (0)

    LOAD_STAGE(0, 0);

    const int NKT = DMODEL / BK;     // 16 stages
    for (int kt = 0; kt < NKT; ++kt) {
        const int cur = kt & 1;
        if (kt + 1 < NKT) {
            LOAD_STAGE(kt + 1, cur ^ 1);
            cp_wait<1>();
        } else {
            cp_wait<0>();
        }
        __syncthreads();

        const __half* Ah_ = pAh[cur];
        const __half* Al_ = pAl[cur];
        const __half* Bh_ = pBh[cur];
        const __half* Bl_ = pBl[cur];

#pragma unroll
        for (int ks = 0; ks < 2; ++ks) {
            const int k0 = ks * 16;

            // B fragments for all 8 n-atoms (hi & lo)
            uint32_t bh[8][2], bl[8][2];
#pragma unroll
            for (int na = 0; na < 8; ++na) {
                const int rowb = wn + na * 8 + r;
                const int o0 = rowb * PADH + k0 + 2 * cq;
                bh[na][0] = *(const uint32_t*)&Bh_[o0];
                bh[na][1] = *(const uint32_t*)&Bh_[o0 + 8];
                bl[na][0] = *(const uint32_t*)&Bl_[o0];
                bl[na][1] = *(const uint32_t*)&Bl_[o0 + 8];
            }

#pragma unroll
            for (int ma = 0; ma < 4; ++ma) {
                const int row = wm + ma * 16 + r;
                const int o0 = row * PADH + k0 + 2 * cq;
                const int o1 = (row + 8) * PADH + k0 + 2 * cq;
                uint32_t ah[4], al[4];
                ah[0] = *(const uint32_t*)&Ah_[o0];
                ah[1] = *(const uint32_t*)&Ah_[o1];
                ah[2] = *(const uint32_t*)&Ah_[o0 + 8];
                ah[3] = *(const uint32_t*)&Ah_[o1 + 8];
                al[0] = *(const uint32_t*)&Al_[o0];
                al[1] = *(const uint32_t*)&Al_[o1];
                al[2] = *(const uint32_t*)&Al_[o0 + 8];
                al[3] = *(const uint32_t*)&Al_[o1 + 8];
#pragma unroll
                for (int na = 0; na < 8; ++na) {
                    mma_f16(acc[ma][na], ah, bh[na]);
                    mma_f16(acc[ma][na], ah, bl[na]);
                    mma_f16(acc[ma][na], al, bh[na]);
                }
            }
        }
        __syncthreads();
    }
#undef LOAD_STAGE

    // epilogue: bias + float2 stores
#pragma unroll
    for (int na = 0; na < 8; ++na) {
        const int col = n0 + wn + na * 8 + 2 * cq;
        const float2 bv = *(const float2*)(bias + col);
#pragma unroll
        for (int ma = 0; ma < 4; ++ma) {
            const int row = m0 + wm + ma * 16 + r;
            float2 v0, v1;
            v0.x = acc[ma][na][0] + bv.x;
            v0.y = acc[ma][na][1] + bv.y;
            v1.x = acc[ma][na][2] + bv.x;
            v1.y = acc[ma][na][3] + bv.y;
            *(float2*)(C + (size_t)row * DMODEL + col)       = v0;
            *(float2*)(C + (size_t)(row + 8) * DMODEL + col) = v1;
        }
    }
}

// ---------------------------------------------------------------------------
// Per-sample head-mixing attention (fp32, unchanged — correct & cheap).
// ---------------------------------------------------------------------------
__global__ __launch_bounds__(128)
void attention_kernel(const float* __restrict__ q1, const float* __restrict__ k1,
                      const float* __restrict__ v1, const float* __restrict__ q2,
                      const float* __restrict__ k2, const float* __restrict__ v2,
                      float* __restrict__ o1, float* __restrict__ o2)
{
    __shared__ float sq[4][NHEADS][68];
    __shared__ float sk[4][NHEADS][68];
    __shared__ float sv[4][NHEADS][68];
    __shared__ float ss[4][NHEADS][NHEADS];

    const int w = threadIdx.x >> 5;
    const int l = threadIdx.x & 31;
    const int s = blockIdx.x * 4 + w;

    const float* Q[2] = { q1 + (size_t)s * DMODEL, q2 + (size_t)s * DMODEL };
    const float* K[2] = { k1 + (size_t)s * DMODEL, k2 + (size_t)s * DMODEL };
    const float* V[2] = { v1 + (size_t)s * DMODEL, v2 + (size_t)s * DMODEL };
    float*       O[2] = { o1 + (size_t)s * DMODEL, o2 + (size_t)s * DMODEL };

    for (int side = 0; side < 2; ++side) {
        const float* q = Q[side];
        const float* k = K[side];
        const float* v = V[side];

#pragma unroll
        for (int i = 0; i < 16; ++i) {
            const int idx = i * 32 + l;
            const int h = idx >> 6, d = idx & 63;
            sq[w][h][d] = q[idx];
            sk[w][h][d] = k[idx];
            sv[w][h][d] = v[idx];
        }
        __syncwarp();

#pragma unroll
        for (int pp = 0; pp < 2; ++pp) {
            const int p = l + pp * 32;
            const int h = p >> 3, e = p & 7;
            float acc = 0.f;
#pragma unroll
            for (int d = 0; d < DHEAD; ++d)
                acc = fmaf(sq[w][h][d], sk[w][e][d], acc);
            ss[w][h][e] = acc * 0.125f;
        }
        __syncwarp();

        if (l < NHEADS) {
            float m = -1e30f;
#pragma unroll
            for (int e = 0; e < NHEADS; ++e) m = fmaxf(m, ss[w][l][e]);
            float ex[NHEADS];
            float sum = 0.f;
#pragma unroll
            for (int e = 0; e < NHEADS; ++e) { ex[e] = expf(ss[w][l][e] - m); sum += ex[e]; }
            const float inv = 1.f / sum;
#pragma unroll
            for (int e = 0; e < NHEADS; ++e) ss[w][l][e] = ex[e] * inv;
        }
        __syncwarp();

#pragma unroll
        for (int dd = 0; dd < 2; ++dd) {
            const int d = l + dd * 32;
#pragma unroll
            for (int h = 0; h < NHEADS; ++h) {
                float acc = 0.f;
#pragma unroll
                for (int e = 0; e < NHEADS; ++e)
                    acc = fmaf(ss[w][h][e], sv[w][e][d], acc);
                O[side][h * DHEAD + d] = acc;
            }
        }
        __syncwarp();
    }
}

// ---------------------------------------------------------------------------
// kernel_launch
// ---------------------------------------------------------------------------
extern "C" void kernel_launch(void* const* d_in, const int* in_sizes, int n_in,
                              void* d_out, int out_size)
{
    const float* prot = (const float*)d_in[0];
    const float* lig  = (const float*)d_in[1];
    const float* Wq1 = (const float*)d_in[2];  const float* bq1 = (const float*)d_in[3];
    const float* Wk1 = (const float*)d_in[4];  const float* bk1 = (const float*)d_in[5];
    const float* Wv1 = (const float*)d_in[6];  const float* bv1 = (const float*)d_in[7];
    const float* Wq2 = (const float*)d_in[8];  const float* bq2 = (const float*)d_in[9];
    const float* Wk2 = (const float*)d_in[10]; const float* bk2 = (const float*)d_in[11];
    const float* Wv2 = (const float*)d_in[12]; const float* bv2 = (const float*)d_in[13];
    const float* Wo1 = (const float*)d_in[14]; const float* bo1 = (const float*)d_in[15];
    const float* Wo2 = (const float*)d_in[16]; const float* bo2 = (const float*)d_in[17];

    float* out      = (float*)d_out;
    float* prot_out = out;
    float* lig_out  = out + (size_t)NB * DMODEL;

    float *q1, *k1, *v1, *q2, *k2, *v2;
    cudaGetSymbolAddress((void**)&q1, g_q1);
    cudaGetSymbolAddress((void**)&k1, g_k1);
    cudaGetSymbolAddress((void**)&v1, g_v1);
    cudaGetSymbolAddress((void**)&q2, g_q2);
    cudaGetSymbolAddress((void**)&k2, g_k2);
    cudaGetSymbolAddress((void**)&v2, g_v2);

    __half *ph, *pl, *lh, *ll, *o1h, *o1l, *o2h, *o2l, *wh, *wl;
    cudaGetSymbolAddress((void**)&ph,  g_prot_h);
    cudaGetSymbolAddress((void**)&pl,  g_prot_l);
    cudaGetSymbolAddress((void**)&lh,  g_lig_h);
    cudaGetSymbolAddress((void**)&ll,  g_lig_l);
    cudaGetSymbolAddress((void**)&o1h, g_o1_h);
    cudaGetSymbolAddress((void**)&o1l, g_o1_l);
    cudaGetSymbolAddress((void**)&o2h, g_o2_h);
    cudaGetSymbolAddress((void**)&o2l, g_o2_l);
    cudaGetSymbolAddress((void**)&wh,  g_W_h);
    cudaGetSymbolAddress((void**)&wl,  g_W_l);

    const int NE2 = NB * DMODEL / 2;

    // 1) split inputs + weights to fp16 hi/lo
    split_kernel<<<4096, 256>>>((const float2*)prot, (__half2*)ph, (__half2*)pl, NE2);
    split_kernel<<<4096, 256>>>((const float2*)lig,  (__half2*)lh, (__half2*)ll, NE2);
    WSplit ws;
    ws.src[0] = Wq1; ws.src[1] = Wk1; ws.src[2] = Wv1; ws.src[3] = Wq2;
    ws.src[4] = Wk2; ws.src[5] = Wv2; ws.src[6] = Wo1; ws.src[7] = Wo2;
    split_w_kernel<<<dim3(64, 8), 256>>>(ws);

    const int DSM = 2 * STAGE_HALVES * 2;   // 122880 bytes
    cudaFuncSetAttribute(gemm_mma_kernel, cudaFuncAttributeMaxDynamicSharedMemorySize, DSM);

    const size_t WSZ = (size_t)DMODEL * DMODEL;
#define WH(i) (wh + (size_t)(i) * WSZ)
#define WL(i) (wl + (size_t)(i) * WSZ)

    // 2) six input projections
    GemmBatch pj;
    pj.Xh[0] = ph; pj.Xl[0] = pl; pj.Wh[0] = WH(0); pj.Wl[0] = WL(0); pj.bias[0] = bq1; pj.C[0] = q1;
    pj.Xh[1] = lh; pj.Xl[1] = ll; pj.Wh[1] = WH(1); pj.Wl[1] = WL(1); pj.bias[1] = bk1; pj.C[1] = k1;
    pj.Xh[2] = lh; pj.Xl[2] = ll; pj.Wh[2] = WH(2); pj.Wl[2] = WL(2); pj.bias[2] = bv1; pj.C[2] = v1;
    pj.Xh[3] = lh; pj.Xl[3] = ll; pj.Wh[3] = WH(3); pj.Wl[3] = WL(3); pj.bias[3] = bq2; pj.C[3] = q2;
    pj.Xh[4] = ph; pj.Xl[4] = pl; pj.Wh[4] = WH(4); pj.Wl[4] = WL(4); pj.bias[4] = bk2; pj.C[4] = k2;
    pj.Xh[5] = ph; pj.Xl[5] = pl; pj.Wh[5] = WH(5); pj.Wl[5] = WL(5); pj.bias[5] = bv2; pj.C[5] = v2;

    dim3 gproj(DMODEL / BN, NB / BM, 6);
    gemm_mma_kernel<<<gproj, 256, DSM>>>(pj);

    // 3) attention (o1 -> q1 buffer, o2 -> q2 buffer)
    attention_kernel<<<NB / 4, 128>>>(q1, k1, v1, q2, k2, v2, q1, q2);

    // 4) split attention outputs
    split_kernel<<<4096, 256>>>((const float2*)q1, (__half2*)o1h, (__half2*)o1l, NE2);
    split_kernel<<<4096, 256>>>((const float2*)q2, (__half2*)o2h, (__half2*)o2l, NE2);

    // 5) output projections
    GemmBatch op;
    op.Xh[0] = o1h; op.Xl[0] = o1l; op.Wh[0] = WH(6); op.Wl[0] = WL(6); op.bias[0] = bo1; op.C[0] = prot_out;
    op.Xh[1] = o2h; op.Xl[1] = o2l; op.Wh[1] = WH(7); op.Wl[1] = WL(7); op.bias[1] = bo2; op.C[1] = lig_out;
    for (int i = 2; i < 6; ++i) {
        op.Xh[i] = o1h; op.Xl[i] = o1l; op.Wh[i] = WH(6); op.Wl[i] = WL(6);
        op.bias[i] = bo1; op.C[i] = prot_out;
    }

    dim3 gout(DMODEL / BN, NB / BM, 2);
    gemm_mma_kernel<<<gout, 256, DSM>>>(op);
#undef WH
#undef WL
}

// round 5
// speedup vs baseline: 1.9158x; 1.0659x over previous
#include <cuda_runtime.h>
#include <cuda_fp16.h>
#include <cstdint>
#include <math.h>

#define NB     32768
#define DMODEL 512
#define NHEADS 8
#define DHEAD  64

// GEMM tiling
#define BM 256
#define BN 128
#define BK 32                     // halves of K per stage
#define PADH 40                   // smem row stride in halves (80B) - conflict-free

// ---------------------------------------------------------------------------
// Scratch buffers
// ---------------------------------------------------------------------------
__device__ float g_q1[(size_t)NB * DMODEL];
__device__ float g_k1[(size_t)NB * DMODEL];
__device__ float g_v1[(size_t)NB * DMODEL];
__device__ float g_q2[(size_t)NB * DMODEL];
__device__ float g_k2[(size_t)NB * DMODEL];
__device__ float g_v2[(size_t)NB * DMODEL];

// fp16 hi/lo split copies
__device__ __half g_prot_h[(size_t)NB * DMODEL];
__device__ __half g_prot_l[(size_t)NB * DMODEL];
__device__ __half g_lig_h [(size_t)NB * DMODEL];
__device__ __half g_lig_l [(size_t)NB * DMODEL];
__device__ __half g_o1_h  [(size_t)NB * DMODEL];
__device__ __half g_o1_l  [(size_t)NB * DMODEL];
__device__ __half g_o2_h  [(size_t)NB * DMODEL];
__device__ __half g_o2_l  [(size_t)NB * DMODEL];
__device__ __half g_W_h[8][DMODEL * DMODEL];
__device__ __half g_W_l[8][DMODEL * DMODEL];

// ---------------------------------------------------------------------------
// helpers
// ---------------------------------------------------------------------------
__device__ __forceinline__ uint32_t smem_u32(const void* p) {
    uint32_t a;
    asm("{ .reg .u64 t; cvta.to.shared.u64 t, %1; cvt.u32.u64 %0, t; }"
        : "=r"(a) : "l"(p));
    return a;
}
__device__ __forceinline__ void cp16(uint32_t dst, const void* src) {
    asm volatile("cp.async.cg.shared.global [%0], [%1], 16;" :: "r"(dst), "l"(src));
}
#define CP_COMMIT() asm volatile("cp.async.commit_group;" ::: "memory")
template <int N> __device__ __forceinline__ void cp_wait() {
    asm volatile("cp.async.wait_group %0;" :: "n"(N) : "memory");
}

// m16n8k16 fp16 MMA, fp32 accumulate (sm_80+, legal in base compute_103 PTX)
__device__ __forceinline__ void mma_f16(float* d, const uint32_t* a, const uint32_t* b) {
    asm volatile(
        "mma.sync.aligned.m16n8k16.row.col.f32.f16.f16.f32 "
        "{%0,%1,%2,%3}, {%4,%5,%6,%7}, {%8,%9}, {%0,%1,%2,%3};"
        : "+f"(d[0]), "+f"(d[1]), "+f"(d[2]), "+f"(d[3])
        : "r"(a[0]), "r"(a[1]), "r"(a[2]), "r"(a[3]), "r"(b[0]), "r"(b[1]));
}

// ---------------------------------------------------------------------------
// fp32 -> (hi fp16, lo fp16) split kernels
// ---------------------------------------------------------------------------
__global__ __launch_bounds__(256)
void split_kernel(const float2* __restrict__ src, __half2* __restrict__ hi,
                  __half2* __restrict__ lo, int n2)
{
    for (int i = blockIdx.x * blockDim.x + threadIdx.x; i < n2;
         i += gridDim.x * blockDim.x) {
        float2 v = src[i];
        __half2 h = __floats2half2_rn(v.x, v.y);
        float2 hb = __half22float2(h);
        __half2 l = __floats2half2_rn(v.x - hb.x, v.y - hb.y);
        hi[i] = h;
        lo[i] = l;
    }
}

struct WSplit { const float* src[8]; };

__global__ __launch_bounds__(256)
void split_w_kernel(WSplit ws)
{
    const int z = blockIdx.y;
    const float2* src = (const float2*)ws.src[z];
    __half2* hi = (__half2*)&g_W_h[z][0];
    __half2* lo = (__half2*)&g_W_l[z][0];
    const int n2 = DMODEL * DMODEL / 2;
    for (int i = blockIdx.x * blockDim.x + threadIdx.x; i < n2;
         i += gridDim.x * blockDim.x) {
        float2 v = src[i];
        __half2 h = __floats2half2_rn(v.x, v.y);
        float2 hb = __half22float2(h);
        __half2 l = __floats2half2_rn(v.x - hb.x, v.y - hb.y);
        hi[i] = h;
        lo[i] = l;
    }
}

// ---------------------------------------------------------------------------
// split-fp16 tensor-core GEMM: C = X @ W^T + bias  (fp32-accuracy via 3 MMAs)
//   CTA tile 256x128, BK=32 halves/stage, 256 threads (8 warps), warp 64x64.
//   MMA order: per ma, pass hh x8, hl x8, lh x8 -> 8 independent HMMAs
//   between any two MMAs hitting the same accumulator (latency hiding).
// ---------------------------------------------------------------------------
struct GemmBatch {
    const __half* Xh[6];
    const __half* Xl[6];
    const __half* Wh[6];
    const __half* Wl[6];
    const float*  bias[6];
    float*        C[6];
};

#define STAGE_HALVES ((BM + BM + BN + BN) * PADH)   // 30720 halves = 61440 B

__global__ __launch_bounds__(256, 1)
void gemm_mma_kernel(GemmBatch args)
{
    const int z = blockIdx.z;
    const __half* __restrict__ Xh = args.Xh[z];
    const __half* __restrict__ Xl = args.Xl[z];
    const __half* __restrict__ Wh = args.Wh[z];
    const __half* __restrict__ Wl = args.Wl[z];
    const float*  __restrict__ bias = args.bias[z];
    float*        __restrict__ C    = args.C[z];

    const int n0 = blockIdx.x * BN;
    const int m0 = blockIdx.y * BM;

    extern __shared__ __half hsm[];
    __half* pAh[2]; __half* pAl[2]; __half* pBh[2]; __half* pBl[2];
#pragma unroll
    for (int s = 0; s < 2; ++s) {
        __half* base = hsm + s * STAGE_HALVES;
        pAh[s] = base;
        pAl[s] = base + BM * PADH;
        pBh[s] = base + 2 * BM * PADH;
        pBl[s] = base + 2 * BM * PADH + BN * PADH;
    }
    uint32_t aAh[2], aAl[2], aBh[2], aBl[2];
#pragma unroll
    for (int s = 0; s < 2; ++s) {
        aAh[s] = smem_u32(pAh[s]);
        aAl[s] = smem_u32(pAl[s]);
        aBh[s] = smem_u32(pBh[s]);
        aBl[s] = smem_u32(pBl[s]);
    }

    const int tid  = threadIdx.x;
    const int wid  = tid >> 5;
    const int lane = tid & 31;
    const int r  = lane >> 2;
    const int cq = lane & 3;

    const int wm = (wid >> 1) * 64;
    const int wn = (wid & 1) * 64;

    float acc[4][8][4];
#pragma unroll
    for (int i = 0; i < 4; ++i)
#pragma unroll
        for (int j = 0; j < 8; ++j)
#pragma unroll
            for (int k = 0; k < 4; ++k)
                acc[i][j][k] = 0.f;

#define LOAD_STAGE(kt, s) do {                                                   \
        const size_t koff = (size_t)(kt) * BK;                                    \
        _Pragma("unroll")                                                        \
        for (int i = 0; i < 4; ++i) {                                            \
            int idx = tid + i * 256; int row = idx >> 2; int ch = idx & 3;       \
            cp16(aAh[s] + row * (PADH * 2) + ch * 16,                            \
                 Xh + (size_t)(m0 + row) * DMODEL + koff + ch * 8);              \
        }                                                                        \
        _Pragma("unroll")                                                        \
        for (int i = 0; i < 4; ++i) {                                            \
            int idx = tid + i * 256; int row = idx >> 2; int ch = idx & 3;       \
            cp16(aAl[s] + row * (PADH * 2) + ch * 16,                            \
                 Xl + (size_t)(m0 + row) * DMODEL + koff + ch * 8);              \
        }                                                                        \
        _Pragma("unroll")                                                        \
        for (int i = 0; i < 2; ++i) {                                            \
            int idx = tid + i * 256; int row = idx >> 2; int ch = idx & 3;       \
            cp16(aBh[s] + row * (PADH * 2) + ch * 16,                            \
                 Wh + (size_t)(n0 + row) * DMODEL + koff + ch * 8);              \
        }                                                                        \
        _Pragma("unroll")                                                        \
        for (int i = 0; i < 2; ++i) {                                            \
            int idx = tid + i * 256; int row = idx >> 2; int ch = idx & 3;       \
            cp16(aBl[s] + row * (PADH * 2) + ch * 16,                            \
                 Wl + (size_t)(n0 + row) * DMODEL + koff + ch * 8);              \
        }                                                                        \
        CP_COMMIT();                                                             \
    } while (0)

    LOAD_STAGE(0, 0);

    const int NKT = DMODEL / BK;     // 16 stages
    for (int kt = 0; kt < NKT; ++kt) {
        const int cur = kt & 1;
        if (kt + 1 < NKT) {
            LOAD_STAGE(kt + 1, cur ^ 1);
            cp_wait<1>();
        } else {
            cp_wait<0>();
        }
        __syncthreads();

        const __half* Ah_ = pAh[cur];
        const __half* Al_ = pAl[cur];
        const __half* Bh_ = pBh[cur];
        const __half* Bl_ = pBl[cur];

#pragma unroll
        for (int ks = 0; ks < 2; ++ks) {
            const int k0 = ks * 16;

            uint32_t bh[8][2], bl[8][2];
#pragma unroll
            for (int na = 0; na < 8; ++na) {
                const int rowb = wn + na * 8 + r;
                const int o0 = rowb * PADH + k0 + 2 * cq;
                bh[na][0] = *(const uint32_t*)&Bh_[o0];
                bh[na][1] = *(const uint32_t*)&Bh_[o0 + 8];
                bl[na][0] = *(const uint32_t*)&Bl_[o0];
                bl[na][1] = *(const uint32_t*)&Bl_[o0 + 8];
            }

#pragma unroll
            for (int ma = 0; ma < 4; ++ma) {
                const int row = wm + ma * 16 + r;
                const int o0 = row * PADH + k0 + 2 * cq;
                const int o1 = (row + 8) * PADH + k0 + 2 * cq;
                uint32_t ah[4], al[4];
                ah[0] = *(const uint32_t*)&Ah_[o0];
                ah[1] = *(const uint32_t*)&Ah_[o1];
                ah[2] = *(const uint32_t*)&Ah_[o0 + 8];
                ah[3] = *(const uint32_t*)&Ah_[o1 + 8];
                al[0] = *(const uint32_t*)&Al_[o0];
                al[1] = *(const uint32_t*)&Al_[o1];
                al[2] = *(const uint32_t*)&Al_[o0 + 8];
                al[3] = *(const uint32_t*)&Al_[o1 + 8];
                // pass-separated: 8 independent MMAs between same-acc hits
#pragma unroll
                for (int na = 0; na < 8; ++na)
                    mma_f16(acc[ma][na], ah, bh[na]);
#pragma unroll
                for (int na = 0; na < 8; ++na)
                    mma_f16(acc[ma][na], ah, bl[na]);
#pragma unroll
                for (int na = 0; na < 8; ++na)
                    mma_f16(acc[ma][na], al, bh[na]);
            }
        }
        __syncthreads();
    }
#undef LOAD_STAGE

    // epilogue: bias + float2 stores
#pragma unroll
    for (int na = 0; na < 8; ++na) {
        const int col = n0 + wn + na * 8 + 2 * cq;
        const float2 bv = *(const float2*)(bias + col);
#pragma unroll
        for (int ma = 0; ma < 4; ++ma) {
            const int row = m0 + wm + ma * 16 + r;
            float2 v0, v1;
            v0.x = acc[ma][na][0] + bv.x;
            v0.y = acc[ma][na][1] + bv.y;
            v1.x = acc[ma][na][2] + bv.x;
            v1.y = acc[ma][na][3] + bv.y;
            *(float2*)(C + (size_t)row * DMODEL + col)       = v0;
            *(float2*)(C + (size_t)(row + 8) * DMODEL + col) = v1;
        }
    }
}

// ---------------------------------------------------------------------------
// Per-sample head-mixing attention. Emits fp16 hi/lo split directly
// (fuses the former split pass for the output projections).
// ---------------------------------------------------------------------------
__global__ __launch_bounds__(128)
void attention_kernel(const float* __restrict__ q1, const float* __restrict__ k1,
                      const float* __restrict__ v1, const float* __restrict__ q2,
                      const float* __restrict__ k2, const float* __restrict__ v2,
                      __half* __restrict__ o1h, __half* __restrict__ o1l,
                      __half* __restrict__ o2h, __half* __restrict__ o2l)
{
    __shared__ float sq[4][NHEADS][68];
    __shared__ float sk[4][NHEADS][68];
    __shared__ float sv[4][NHEADS][68];
    __shared__ float ss[4][NHEADS][NHEADS];

    const int w = threadIdx.x >> 5;
    const int l = threadIdx.x & 31;
    const int s = blockIdx.x * 4 + w;

    const float* Q[2] = { q1 + (size_t)s * DMODEL, q2 + (size_t)s * DMODEL };
    const float* K[2] = { k1 + (size_t)s * DMODEL, k2 + (size_t)s * DMODEL };
    const float* V[2] = { v1 + (size_t)s * DMODEL, v2 + (size_t)s * DMODEL };
    __half* OH[2] = { o1h + (size_t)s * DMODEL, o2h + (size_t)s * DMODEL };
    __half* OL[2] = { o1l + (size_t)s * DMODEL, o2l + (size_t)s * DMODEL };

    for (int side = 0; side < 2; ++side) {
        const float* q = Q[side];
        const float* k = K[side];
        const float* v = V[side];

#pragma unroll
        for (int i = 0; i < 16; ++i) {
            const int idx = i * 32 + l;
            const int h = idx >> 6, d = idx & 63;
            sq[w][h][d] = q[idx];
            sk[w][h][d] = k[idx];
            sv[w][h][d] = v[idx];
        }
        __syncwarp();

#pragma unroll
        for (int pp = 0; pp < 2; ++pp) {
            const int p = l + pp * 32;
            const int h = p >> 3, e = p & 7;
            float acc = 0.f;
#pragma unroll
            for (int d = 0; d < DHEAD; ++d)
                acc = fmaf(sq[w][h][d], sk[w][e][d], acc);
            ss[w][h][e] = acc * 0.125f;
        }
        __syncwarp();

        if (l < NHEADS) {
            float m = -1e30f;
#pragma unroll
            for (int e = 0; e < NHEADS; ++e) m = fmaxf(m, ss[w][l][e]);
            float ex[NHEADS];
            float sum = 0.f;
#pragma unroll
            for (int e = 0; e < NHEADS; ++e) { ex[e] = expf(ss[w][l][e] - m); sum += ex[e]; }
            const float inv = 1.f / sum;
#pragma unroll
            for (int e = 0; e < NHEADS; ++e) ss[w][l][e] = ex[e] * inv;
        }
        __syncwarp();

#pragma unroll
        for (int dd = 0; dd < 2; ++dd) {
            const int d = l + dd * 32;
#pragma unroll
            for (int h = 0; h < NHEADS; ++h) {
                float acc = 0.f;
#pragma unroll
                for (int e = 0; e < NHEADS; ++e)
                    acc = fmaf(ss[w][h][e], sv[w][e][d], acc);
                const __half hv = __float2half_rn(acc);
                const __half lv = __float2half_rn(acc - __half2float(hv));
                OH[side][h * DHEAD + d] = hv;
                OL[side][h * DHEAD + d] = lv;
            }
        }
        __syncwarp();
    }
}

// ---------------------------------------------------------------------------
// kernel_launch
// ---------------------------------------------------------------------------
extern "C" void kernel_launch(void* const* d_in, const int* in_sizes, int n_in,
                              void* d_out, int out_size)
{
    const float* prot = (const float*)d_in[0];
    const float* lig  = (const float*)d_in[1];
    const float* Wq1 = (const float*)d_in[2];  const float* bq1 = (const float*)d_in[3];
    const float* Wk1 = (const float*)d_in[4];  const float* bk1 = (const float*)d_in[5];
    const float* Wv1 = (const float*)d_in[6];  const float* bv1 = (const float*)d_in[7];
    const float* Wq2 = (const float*)d_in[8];  const float* bq2 = (const float*)d_in[9];
    const float* Wk2 = (const float*)d_in[10]; const float* bk2 = (const float*)d_in[11];
    const float* Wv2 = (const float*)d_in[12]; const float* bv2 = (const float*)d_in[13];
    const float* Wo1 = (const float*)d_in[14]; const float* bo1 = (const float*)d_in[15];
    const float* Wo2 = (const float*)d_in[16]; const float* bo2 = (const float*)d_in[17];

    float* out      = (float*)d_out;
    float* prot_out = out;
    float* lig_out  = out + (size_t)NB * DMODEL;

    float *q1, *k1, *v1, *q2, *k2, *v2;
    cudaGetSymbolAddress((void**)&q1, g_q1);
    cudaGetSymbolAddress((void**)&k1, g_k1);
    cudaGetSymbolAddress((void**)&v1, g_v1);
    cudaGetSymbolAddress((void**)&q2, g_q2);
    cudaGetSymbolAddress((void**)&k2, g_k2);
    cudaGetSymbolAddress((void**)&v2, g_v2);

    __half *ph, *pl, *lh, *ll, *o1h, *o1l, *o2h, *o2l, *wh, *wl;
    cudaGetSymbolAddress((void**)&ph,  g_prot_h);
    cudaGetSymbolAddress((void**)&pl,  g_prot_l);
    cudaGetSymbolAddress((void**)&lh,  g_lig_h);
    cudaGetSymbolAddress((void**)&ll,  g_lig_l);
    cudaGetSymbolAddress((void**)&o1h, g_o1_h);
    cudaGetSymbolAddress((void**)&o1l, g_o1_l);
    cudaGetSymbolAddress((void**)&o2h, g_o2_h);
    cudaGetSymbolAddress((void**)&o2l, g_o2_l);
    cudaGetSymbolAddress((void**)&wh,  g_W_h);
    cudaGetSymbolAddress((void**)&wl,  g_W_l);

    const int NE2 = NB * DMODEL / 2;

    // 1) split inputs + weights to fp16 hi/lo
    split_kernel<<<4096, 256>>>((const float2*)prot, (__half2*)ph, (__half2*)pl, NE2);
    split_kernel<<<4096, 256>>>((const float2*)lig,  (__half2*)lh, (__half2*)ll, NE2);
    WSplit ws;
    ws.src[0] = Wq1; ws.src[1] = Wk1; ws.src[2] = Wv1; ws.src[3] = Wq2;
    ws.src[4] = Wk2; ws.src[5] = Wv2; ws.src[6] = Wo1; ws.src[7] = Wo2;
    split_w_kernel<<<dim3(64, 8), 256>>>(ws);

    const int DSM = 2 * STAGE_HALVES * 2;   // 122880 bytes
    cudaFuncSetAttribute(gemm_mma_kernel, cudaFuncAttributeMaxDynamicSharedMemorySize, DSM);

    const size_t WSZ = (size_t)DMODEL * DMODEL;
#define WH(i) (wh + (size_t)(i) * WSZ)
#define WL(i) (wl + (size_t)(i) * WSZ)

    // 2) six input projections
    GemmBatch pj;
    pj.Xh[0] = ph; pj.Xl[0] = pl; pj.Wh[0] = WH(0); pj.Wl[0] = WL(0); pj.bias[0] = bq1; pj.C[0] = q1;
    pj.Xh[1] = lh; pj.Xl[1] = ll; pj.Wh[1] = WH(1); pj.Wl[1] = WL(1); pj.bias[1] = bk1; pj.C[1] = k1;
    pj.Xh[2] = lh; pj.Xl[2] = ll; pj.Wh[2] = WH(2); pj.Wl[2] = WL(2); pj.bias[2] = bv1; pj.C[2] = v1;
    pj.Xh[3] = lh; pj.Xl[3] = ll; pj.Wh[3] = WH(3); pj.Wl[3] = WL(3); pj.bias[3] = bq2; pj.C[3] = q2;
    pj.Xh[4] = ph; pj.Xl[4] = pl; pj.Wh[4] = WH(4); pj.Wl[4] = WL(4); pj.bias[4] = bk2; pj.C[4] = k2;
    pj.Xh[5] = ph; pj.Xl[5] = pl; pj.Wh[5] = WH(5); pj.Wl[5] = WL(5); pj.bias[5] = bv2; pj.C[5] = v2;

    dim3 gproj(DMODEL / BN, NB / BM, 6);
    gemm_mma_kernel<<<gproj, 256, DSM>>>(pj);

    // 3) attention (emits hi/lo fp16 directly)
    attention_kernel<<<NB / 4, 128>>>(q1, k1, v1, q2, k2, v2, o1h, o1l, o2h, o2l);

    // 4) output projections
    GemmBatch op;
    op.Xh[0] = o1h; op.Xl[0] = o1l; op.Wh[0] = WH(6); op.Wl[0] = WL(6); op.bias[0] = bo1; op.C[0] = prot_out;
    op.Xh[1] = o2h; op.Xl[1] = o2l; op.Wh[1] = WH(7); op.Wl[1] = WL(7); op.bias[1] = bo2; op.C[1] = lig_out;
    for (int i = 2; i < 6; ++i) {
        op.Xh[i] = o1h; op.Xl[i] = o1l; op.Wh[i] = WH(6); op.Wl[i] = WL(6);
        op.bias[i] = bo1; op.C[i] = prot_out;
    }

    dim3 gout(DMODEL / BN, NB / BM, 2);
    gemm_mma_kernel<<<gout, 256, DSM>>>(op);
#undef WH
#undef WL
}

// round 6
// speedup vs baseline: 2.3508x; 1.2271x over previous
#include <cuda_runtime.h>
#include <cuda_fp16.h>
#include <cstdint>
#include <math.h>

#define NB     32768
#define DMODEL 512
#define NHEADS 8
#define DHEAD  64

// GEMM tiling
#define BM 128
#define BN 128
#define BK 32                 // K halves per stage
#define NSTAGE 3
#define STAGE_BYTES 32768     // A 16KB + B 16KB (128 rows x 128B each)

// ---------------------------------------------------------------------------
// Scratch buffers
// ---------------------------------------------------------------------------
__device__ float g_q1[(size_t)NB * DMODEL];
__device__ float g_k1[(size_t)NB * DMODEL];
__device__ float g_v1[(size_t)NB * DMODEL];
__device__ float g_q2[(size_t)NB * DMODEL];
__device__ float g_k2[(size_t)NB * DMODEL];
__device__ float g_v2[(size_t)NB * DMODEL];

__device__ __half g_prot_h[(size_t)NB * DMODEL];
__device__ __half g_prot_l[(size_t)NB * DMODEL];
__device__ __half g_lig_h [(size_t)NB * DMODEL];
__device__ __half g_lig_l [(size_t)NB * DMODEL];
__device__ __half g_o1_h  [(size_t)NB * DMODEL];
__device__ __half g_o1_l  [(size_t)NB * DMODEL];
__device__ __half g_o2_h  [(size_t)NB * DMODEL];
__device__ __half g_o2_l  [(size_t)NB * DMODEL];
__device__ __half g_W_h[8][DMODEL * DMODEL];
__device__ __half g_W_l[8][DMODEL * DMODEL];

// ---------------------------------------------------------------------------
// helpers
// ---------------------------------------------------------------------------
__device__ __forceinline__ uint32_t smem_u32(const void* p) {
    uint32_t a;
    asm("{ .reg .u64 t; cvta.to.shared.u64 t, %1; cvt.u32.u64 %0, t; }"
        : "=r"(a) : "l"(p));
    return a;
}
__device__ __forceinline__ void cp16(uint32_t dst, const void* src) {
    asm volatile("cp.async.cg.shared.global [%0], [%1], 16;" :: "r"(dst), "l"(src));
}
#define CP_COMMIT() asm volatile("cp.async.commit_group;" ::: "memory")
template <int N> __device__ __forceinline__ void cp_wait() {
    asm volatile("cp.async.wait_group %0;" :: "n"(N) : "memory");
}

__device__ __forceinline__ void ldm_x4(uint32_t* d, uint32_t addr) {
    asm volatile("ldmatrix.sync.aligned.m8n8.x4.shared.b16 {%0,%1,%2,%3}, [%4];"
                 : "=r"(d[0]), "=r"(d[1]), "=r"(d[2]), "=r"(d[3]) : "r"(addr));
}

__device__ __forceinline__ void mma_f16(float* d, const uint32_t* a, const uint32_t* b) {
    asm volatile(
        "mma.sync.aligned.m16n8k16.row.col.f32.f16.f16.f32 "
        "{%0,%1,%2,%3}, {%4,%5,%6,%7}, {%8,%9}, {%0,%1,%2,%3};"
        : "+f"(d[0]), "+f"(d[1]), "+f"(d[2]), "+f"(d[3])
        : "r"(a[0]), "r"(a[1]), "r"(a[2]), "r"(a[3]), "r"(b[0]), "r"(b[1]));
}

// ---------------------------------------------------------------------------
// fp32 -> (hi fp16, lo fp16) split kernels
// ---------------------------------------------------------------------------
__global__ __launch_bounds__(256)
void split_kernel(const float2* __restrict__ src, __half2* __restrict__ hi,
                  __half2* __restrict__ lo, int n2)
{
    for (int i = blockIdx.x * blockDim.x + threadIdx.x; i < n2;
         i += gridDim.x * blockDim.x) {
        float2 v = src[i];
        __half2 h = __floats2half2_rn(v.x, v.y);
        float2 hb = __half22float2(h);
        __half2 l = __floats2half2_rn(v.x - hb.x, v.y - hb.y);
        hi[i] = h;
        lo[i] = l;
    }
}

struct WSplit { const float* src[8]; };

__global__ __launch_bounds__(256)
void split_w_kernel(WSplit ws)
{
    const int z = blockIdx.y;
    const float2* src = (const float2*)ws.src[z];
    __half2* hi = (__half2*)&g_W_h[z][0];
    __half2* lo = (__half2*)&g_W_l[z][0];
    const int n2 = DMODEL * DMODEL / 2;
    for (int i = blockIdx.x * blockDim.x + threadIdx.x; i < n2;
         i += gridDim.x * blockDim.x) {
        float2 v = src[i];
        __half2 h = __floats2half2_rn(v.x, v.y);
        float2 hb = __half22float2(h);
        __half2 l = __floats2half2_rn(v.x - hb.x, v.y - hb.y);
        hi[i] = h;
        lo[i] = l;
    }
}

// ---------------------------------------------------------------------------
// split-fp16 tensor-core GEMM: C = X @ W^T + bias
//   CTA tile 128x128, 256 thr (8 warps, 4m x 2n), warp tile 32x64.
//   SMEM row = 128B: [hi k0..31 | lo k0..31] halves, XOR-swizzled chunks.
//   3-stage cp.async pipeline, ONE __syncthreads per k-iteration.
//   2 CTAs/SM (96KB smem, <=128 regs).
// ---------------------------------------------------------------------------
struct GemmBatch {
    const __half* Xh[6];
    const __half* Xl[6];
    const __half* Wh[6];
    const __half* Wl[6];
    const float*  bias[6];
    float*        C[6];
};

__global__ __launch_bounds__(256, 2)
void gemm_mma_kernel(GemmBatch args)
{
    const int z = blockIdx.z;
    const __half* __restrict__ Xh = args.Xh[z];
    const __half* __restrict__ Xl = args.Xl[z];
    const __half* __restrict__ Wh = args.Wh[z];
    const __half* __restrict__ Wl = args.Wl[z];
    const float*  __restrict__ bias = args.bias[z];
    float*        __restrict__ C    = args.C[z];

    const int n0 = blockIdx.x * BN;
    const int m0 = blockIdx.y * BM;

    extern __shared__ __align__(128) char smraw[];
    const uint32_t sbase = smem_u32(smraw);

    const int tid  = threadIdx.x;
    const int wid  = tid >> 5;
    const int lane = tid & 31;
    const int r  = lane >> 2;
    const int cq = lane & 3;

    const int wm = (wid >> 1) * 32;   // 0,32,64,96
    const int wn = (wid & 1) * 64;    // 0,64

    // --- ldmatrix lane address pre-computation (byte offsets within tile) ---
    // A: x4 covers one 16x16 (hi or lo): lanes 0-7 m-low/k-low, 8-15 m-high/k-low,
    //    16-23 m-low/k-high, 24-31 m-high/k-high.
    const int a_row_in16 = (lane & 7) + ((lane >> 3) & 1) * 8;
    const int a_kh       = lane >> 4;                 // 0/1
    // B: x4 covers 2 n-atoms (16 n-rows) x k16: lanes 0-7 atom0/k-low,
    //    8-15 atom0/k-high, 16-23 atom1/k-low, 24-31 atom1/k-high.
    const int b_row_in16 = (lane & 7) + ((lane >> 4) & 1) * 8;
    const int b_kh       = (lane >> 3) & 1;

    float acc[2][8][4];
#pragma unroll
    for (int i = 0; i < 2; ++i)
#pragma unroll
        for (int j = 0; j < 8; ++j)
#pragma unroll
            for (int k = 0; k < 4; ++k)
                acc[i][j][k] = 0.f;

    // loader: 2048 x 16B chunks per stage (A 1024 + B 1024), 8 per thread.
    // A row layout: chunks 0-3 = hi k0..31, chunks 4-7 = lo k0..31, swizzled.
#define LOAD_STAGE(kt, s) do {                                                  \
        const uint32_t st = sbase + (s) * STAGE_BYTES;                          \
        const size_t koff = (size_t)(kt) * BK;                                  \
        _Pragma("unroll")                                                       \
        for (int j = 0; j < 4; ++j) {                                           \
            int idx = tid + j * 256; int row = idx >> 3; int c = idx & 7;       \
            const __half* src = (c < 4) ? Xh : Xl;                              \
            cp16(st + row * 128 + ((c ^ (row & 7)) << 4),                       \
                 src + (size_t)(m0 + row) * DMODEL + koff + (c & 3) * 8);       \
        }                                                                       \
        _Pragma("unroll")                                                       \
        for (int j = 0; j < 4; ++j) {                                           \
            int idx = tid + j * 256; int row = idx >> 3; int c = idx & 7;       \
            const __half* src = (c < 4) ? Wh : Wl;                              \
            cp16(st + 16384 + row * 128 + ((c ^ (row & 7)) << 4),               \
                 src + (size_t)(n0 + row) * DMODEL + koff + (c & 3) * 8);       \
        }                                                                       \
        CP_COMMIT();                                                            \
    } while (0)

    LOAD_STAGE(0, 0);
    LOAD_STAGE(1, 1);

    const int NKT = DMODEL / BK;   // 16
    for (int kt = 0; kt < NKT; ++kt) {
        cp_wait<1>();              // stage kt resident (kt+1 still in flight)
        __syncthreads();           // all warps done with stage (kt-1)%3 reads
        if (kt + 2 < NKT) {
            LOAD_STAGE(kt + 2, (kt + 2) % 3);
        } else {
            CP_COMMIT();           // empty group keeps wait<1> arithmetic uniform
        }

        const uint32_t aB = sbase + (kt % 3) * STAGE_BYTES;
        const uint32_t bB = aB + 16384;

#pragma unroll
        for (int ks = 0; ks < 2; ++ks) {
            // A fragments (hi & lo) for both 16-row m-atoms
            uint32_t ah[2][4], al[2][4];
#pragma unroll
            for (int ma = 0; ma < 2; ++ma) {
                const int arow = wm + ma * 16 + a_row_in16;
                const int sw = arow & 7;
                const uint32_t rb = aB + arow * 128;
                ldm_x4(ah[ma], rb + (((2 * ks + a_kh) ^ sw) << 4));
                ldm_x4(al[ma], rb + (((2 * ks + a_kh + 4) ^ sw) << 4));
            }

#pragma unroll
            for (int grp = 0; grp < 2; ++grp) {
                // B fragments for 4 n-atoms (2 ldmatrix.x4 hi + 2 lo)
                uint32_t bh[4][2], bl[4][2];
#pragma unroll
                for (int pair = 0; pair < 2; ++pair) {
                    const int brow = wn + grp * 32 + pair * 16 + b_row_in16;
                    const int sw = brow & 7;
                    const uint32_t rb = bB + brow * 128;
                    uint32_t th[4], tl[4];
                    ldm_x4(th, rb + (((2 * ks + b_kh) ^ sw) << 4));
                    ldm_x4(tl, rb + (((2 * ks + b_kh + 4) ^ sw) << 4));
                    bh[pair * 2 + 0][0] = th[0]; bh[pair * 2 + 0][1] = th[1];
                    bh[pair * 2 + 1][0] = th[2]; bh[pair * 2 + 1][1] = th[3];
                    bl[pair * 2 + 0][0] = tl[0]; bl[pair * 2 + 0][1] = tl[1];
                    bl[pair * 2 + 1][0] = tl[2]; bl[pair * 2 + 1][1] = tl[3];
                }
                // pass-separated MMAs: same-acc distance = 8
#pragma unroll
                for (int i = 0; i < 4; ++i) {
                    mma_f16(acc[0][grp * 4 + i], ah[0], bh[i]);
                    mma_f16(acc[1][grp * 4 + i], ah[1], bh[i]);
                }
#pragma unroll
                for (int i = 0; i < 4; ++i) {
                    mma_f16(acc[0][grp * 4 + i], ah[0], bl[i]);
                    mma_f16(acc[1][grp * 4 + i], ah[1], bl[i]);
                }
#pragma unroll
                for (int i = 0; i < 4; ++i) {
                    mma_f16(acc[0][grp * 4 + i], al[0], bh[i]);
                    mma_f16(acc[1][grp * 4 + i], al[1], bh[i]);
                }
            }
        }
    }
#undef LOAD_STAGE

    // epilogue: acc[ma][j] -> n offset = (j>>2)*32 + (j&3)*8
#pragma unroll
    for (int j = 0; j < 8; ++j) {
        const int col = n0 + wn + (j >> 2) * 32 + (j & 3) * 8 + 2 * cq;
        const float2 bv = *(const float2*)(bias + col);
#pragma unroll
        for (int ma = 0; ma < 2; ++ma) {
            const int row = m0 + wm + ma * 16 + r;
            float2 v0, v1;
            v0.x = acc[ma][j][0] + bv.x;
            v0.y = acc[ma][j][1] + bv.y;
            v1.x = acc[ma][j][2] + bv.x;
            v1.y = acc[ma][j][3] + bv.y;
            *(float2*)(C + (size_t)row * DMODEL + col)       = v0;
            *(float2*)(C + (size_t)(row + 8) * DMODEL + col) = v1;
        }
    }
}

// ---------------------------------------------------------------------------
// Per-sample head-mixing attention; emits fp16 hi/lo directly.
// ---------------------------------------------------------------------------
__global__ __launch_bounds__(128)
void attention_kernel(const float* __restrict__ q1, const float* __restrict__ k1,
                      const float* __restrict__ v1, const float* __restrict__ q2,
                      const float* __restrict__ k2, const float* __restrict__ v2,
                      __half* __restrict__ o1h, __half* __restrict__ o1l,
                      __half* __restrict__ o2h, __half* __restrict__ o2l)
{
    __shared__ float sq[4][NHEADS][68];
    __shared__ float sk[4][NHEADS][68];
    __shared__ float sv[4][NHEADS][68];
    __shared__ float ss[4][NHEADS][NHEADS];

    const int w = threadIdx.x >> 5;
    const int l = threadIdx.x & 31;
    const int s = blockIdx.x * 4 + w;

    const float* Q[2] = { q1 + (size_t)s * DMODEL, q2 + (size_t)s * DMODEL };
    const float* K[2] = { k1 + (size_t)s * DMODEL, k2 + (size_t)s * DMODEL };
    const float* V[2] = { v1 + (size_t)s * DMODEL, v2 + (size_t)s * DMODEL };
    __half* OH[2] = { o1h + (size_t)s * DMODEL, o2h + (size_t)s * DMODEL };
    __half* OL[2] = { o1l + (size_t)s * DMODEL, o2l + (size_t)s * DMODEL };

    for (int side = 0; side < 2; ++side) {
        const float* q = Q[side];
        const float* k = K[side];
        const float* v = V[side];

#pragma unroll
        for (int i = 0; i < 16; ++i) {
            const int idx = i * 32 + l;
            const int h = idx >> 6, d = idx & 63;
            sq[w][h][d] = q[idx];
            sk[w][h][d] = k[idx];
            sv[w][h][d] = v[idx];
        }
        __syncwarp();

#pragma unroll
        for (int pp = 0; pp < 2; ++pp) {
            const int p = l + pp * 32;
            const int h = p >> 3, e = p & 7;
            float acc = 0.f;
#pragma unroll
            for (int d = 0; d < DHEAD; ++d)
                acc = fmaf(sq[w][h][d], sk[w][e][d], acc);
            ss[w][h][e] = acc * 0.125f;
        }
        __syncwarp();

        if (l < NHEADS) {
            float m = -1e30f;
#pragma unroll
            for (int e = 0; e < NHEADS; ++e) m = fmaxf(m, ss[w][l][e]);
            float ex[NHEADS];
            float sum = 0.f;
#pragma unroll
            for (int e = 0; e < NHEADS; ++e) { ex[e] = expf(ss[w][l][e] - m); sum += ex[e]; }
            const float inv = 1.f / sum;
#pragma unroll
            for (int e = 0; e < NHEADS; ++e) ss[w][l][e] = ex[e] * inv;
        }
        __syncwarp();

#pragma unroll
        for (int dd = 0; dd < 2; ++dd) {
            const int d = l + dd * 32;
#pragma unroll
            for (int h = 0; h < NHEADS; ++h) {
                float acc = 0.f;
#pragma unroll
                for (int e = 0; e < NHEADS; ++e)
                    acc = fmaf(ss[w][h][e], sv[w][e][d], acc);
                const __half hv = __float2half_rn(acc);
                const __half lv = __float2half_rn(acc - __half2float(hv));
                OH[side][h * DHEAD + d] = hv;
                OL[side][h * DHEAD + d] = lv;
            }
        }
        __syncwarp();
    }
}

// ---------------------------------------------------------------------------
// kernel_launch
// ---------------------------------------------------------------------------
extern "C" void kernel_launch(void* const* d_in, const int* in_sizes, int n_in,
                              void* d_out, int out_size)
{
    const float* prot = (const float*)d_in[0];
    const float* lig  = (const float*)d_in[1];
    const float* Wq1 = (const float*)d_in[2];  const float* bq1 = (const float*)d_in[3];
    const float* Wk1 = (const float*)d_in[4];  const float* bk1 = (const float*)d_in[5];
    const float* Wv1 = (const float*)d_in[6];  const float* bv1 = (const float*)d_in[7];
    const float* Wq2 = (const float*)d_in[8];  const float* bq2 = (const float*)d_in[9];
    const float* Wk2 = (const float*)d_in[10]; const float* bk2 = (const float*)d_in[11];
    const float* Wv2 = (const float*)d_in[12]; const float* bv2 = (const float*)d_in[13];
    const float* Wo1 = (const float*)d_in[14]; const float* bo1 = (const float*)d_in[15];
    const float* Wo2 = (const float*)d_in[16]; const float* bo2 = (const float*)d_in[17];

    float* out      = (float*)d_out;
    float* prot_out = out;
    float* lig_out  = out + (size_t)NB * DMODEL;

    float *q1, *k1, *v1, *q2, *k2, *v2;
    cudaGetSymbolAddress((void**)&q1, g_q1);
    cudaGetSymbolAddress((void**)&k1, g_k1);
    cudaGetSymbolAddress((void**)&v1, g_v1);
    cudaGetSymbolAddress((void**)&q2, g_q2);
    cudaGetSymbolAddress((void**)&k2, g_k2);
    cudaGetSymbolAddress((void**)&v2, g_v2);

    __half *ph, *pl, *lh, *ll, *o1h, *o1l, *o2h, *o2l, *wh, *wl;
    cudaGetSymbolAddress((void**)&ph,  g_prot_h);
    cudaGetSymbolAddress((void**)&pl,  g_prot_l);
    cudaGetSymbolAddress((void**)&lh,  g_lig_h);
    cudaGetSymbolAddress((void**)&ll,  g_lig_l);
    cudaGetSymbolAddress((void**)&o1h, g_o1_h);
    cudaGetSymbolAddress((void**)&o1l, g_o1_l);
    cudaGetSymbolAddress((void**)&o2h, g_o2_h);
    cudaGetSymbolAddress((void**)&o2l, g_o2_l);
    cudaGetSymbolAddress((void**)&wh,  g_W_h);
    cudaGetSymbolAddress((void**)&wl,  g_W_l);

    const int NE2 = NB * DMODEL / 2;

    split_kernel<<<4096, 256>>>((const float2*)prot, (__half2*)ph, (__half2*)pl, NE2);
    split_kernel<<<4096, 256>>>((const float2*)lig,  (__half2*)lh, (__half2*)ll, NE2);
    WSplit ws;
    ws.src[0] = Wq1; ws.src[1] = Wk1; ws.src[2] = Wv1; ws.src[3] = Wq2;
    ws.src[4] = Wk2; ws.src[5] = Wv2; ws.src[6] = Wo1; ws.src[7] = Wo2;
    split_w_kernel<<<dim3(64, 8), 256>>>(ws);

    const int DSM = NSTAGE * STAGE_BYTES;   // 98304
    cudaFuncSetAttribute(gemm_mma_kernel, cudaFuncAttributeMaxDynamicSharedMemorySize, DSM);

    const size_t WSZ = (size_t)DMODEL * DMODEL;
#define WH(i) (wh + (size_t)(i) * WSZ)
#define WL(i) (wl + (size_t)(i) * WSZ)

    GemmBatch pj;
    pj.Xh[0] = ph; pj.Xl[0] = pl; pj.Wh[0] = WH(0); pj.Wl[0] = WL(0); pj.bias[0] = bq1; pj.C[0] = q1;
    pj.Xh[1] = lh; pj.Xl[1] = ll; pj.Wh[1] = WH(1); pj.Wl[1] = WL(1); pj.bias[1] = bk1; pj.C[1] = k1;
    pj.Xh[2] = lh; pj.Xl[2] = ll; pj.Wh[2] = WH(2); pj.Wl[2] = WL(2); pj.bias[2] = bv1; pj.C[2] = v1;
    pj.Xh[3] = lh; pj.Xl[3] = ll; pj.Wh[3] = WH(3); pj.Wl[3] = WL(3); pj.bias[3] = bq2; pj.C[3] = q2;
    pj.Xh[4] = ph; pj.Xl[4] = pl; pj.Wh[4] = WH(4); pj.Wl[4] = WL(4); pj.bias[4] = bk2; pj.C[4] = k2;
    pj.Xh[5] = ph; pj.Xl[5] = pl; pj.Wh[5] = WH(5); pj.Wl[5] = WL(5); pj.bias[5] = bv2; pj.C[5] = v2;

    dim3 gproj(DMODEL / BN, NB / BM, 6);       // n fastest -> A stripe L2 reuse
    gemm_mma_kernel<<<gproj, 256, DSM>>>(pj);

    attention_kernel<<<NB / 4, 128>>>(q1, k1, v1, q2, k2, v2, o1h, o1l, o2h, o2l);

    GemmBatch op;
    op.Xh[0] = o1h; op.Xl[0] = o1l; op.Wh[0] = WH(6); op.Wl[0] = WL(6); op.bias[0] = bo1; op.C[0] = prot_out;
    op.Xh[1] = o2h; op.Xl[1] = o2l; op.Wh[1] = WH(7); op.Wl[1] = WL(7); op.bias[1] = bo2; op.C[1] = lig_out;
    for (int i = 2; i < 6; ++i) {
        op.Xh[i] = o1h; op.Xl[i] = o1l; op.Wh[i] = WH(6); op.Wl[i] = WL(6);
        op.bias[i] = bo1; op.C[i] = prot_out;
    }

    dim3 gout(DMODEL / BN, NB / BM, 2);
    gemm_mma_kernel<<<gout, 256, DSM>>>(op);
#undef WH
#undef WL
}

// round 7
// speedup vs baseline: 2.4032x; 1.0223x over previous
#include <cuda_runtime.h>
#include <cuda_fp16.h>
#include <cstdint>
#include <math.h>

#define NB     32768
#define DMODEL 512
#define NHEADS 8
#define DHEAD  64

// GEMM tiling
#define BM 128
#define BN 128
#define BK 32                 // K halves per stage
#define NSTAGE 3
#define STAGE_BYTES 32768     // A 16KB + B 16KB (128 rows x 128B each)

// ---------------------------------------------------------------------------
// Scratch buffers
// ---------------------------------------------------------------------------
__device__ float g_q1[(size_t)NB * DMODEL];
__device__ float g_k1[(size_t)NB * DMODEL];
__device__ float g_v1[(size_t)NB * DMODEL];
__device__ float g_q2[(size_t)NB * DMODEL];
__device__ float g_k2[(size_t)NB * DMODEL];
__device__ float g_v2[(size_t)NB * DMODEL];

__device__ __half g_prot_h[(size_t)NB * DMODEL];
__device__ __half g_prot_l[(size_t)NB * DMODEL];
__device__ __half g_lig_h [(size_t)NB * DMODEL];
__device__ __half g_lig_l [(size_t)NB * DMODEL];
__device__ __half g_o1_h  [(size_t)NB * DMODEL];
__device__ __half g_o1_l  [(size_t)NB * DMODEL];
__device__ __half g_o2_h  [(size_t)NB * DMODEL];
__device__ __half g_o2_l  [(size_t)NB * DMODEL];
__device__ __half g_W_h[8][DMODEL * DMODEL];
__device__ __half g_W_l[8][DMODEL * DMODEL];

// ---------------------------------------------------------------------------
// helpers
// ---------------------------------------------------------------------------
__device__ __forceinline__ uint32_t smem_u32(const void* p) {
    uint32_t a;
    asm("{ .reg .u64 t; cvta.to.shared.u64 t, %1; cvt.u32.u64 %0, t; }"
        : "=r"(a) : "l"(p));
    return a;
}
__device__ __forceinline__ void cp16(uint32_t dst, const void* src) {
    asm volatile("cp.async.cg.shared.global [%0], [%1], 16;" :: "r"(dst), "l"(src));
}
#define CP_COMMIT() asm volatile("cp.async.commit_group;" ::: "memory")
template <int N> __device__ __forceinline__ void cp_wait() {
    asm volatile("cp.async.wait_group %0;" :: "n"(N) : "memory");
}

__device__ __forceinline__ void ldm_x4(uint32_t* d, uint32_t addr) {
    asm volatile("ldmatrix.sync.aligned.m8n8.x4.shared.b16 {%0,%1,%2,%3}, [%4];"
                 : "=r"(d[0]), "=r"(d[1]), "=r"(d[2]), "=r"(d[3]) : "r"(addr));
}

__device__ __forceinline__ void mma_f16(float* d, const uint32_t* a, const uint32_t* b) {
    asm volatile(
        "mma.sync.aligned.m16n8k16.row.col.f32.f16.f16.f32 "
        "{%0,%1,%2,%3}, {%4,%5,%6,%7}, {%8,%9}, {%0,%1,%2,%3};"
        : "+f"(d[0]), "+f"(d[1]), "+f"(d[2]), "+f"(d[3])
        : "r"(a[0]), "r"(a[1]), "r"(a[2]), "r"(a[3]), "r"(b[0]), "r"(b[1]));
}

// ---------------------------------------------------------------------------
// fp32 -> (hi fp16, lo fp16) split kernels
// ---------------------------------------------------------------------------
struct SplitBatch {
    const float2* src[2];
    __half2* hi[2];
    __half2* lo[2];
};

__global__ __launch_bounds__(256)
void split_kernel(SplitBatch sb, int n2)
{
    const int z = blockIdx.y;
    const float2* __restrict__ src = sb.src[z];
    __half2* __restrict__ hi = sb.hi[z];
    __half2* __restrict__ lo = sb.lo[z];
    for (int i = blockIdx.x * blockDim.x + threadIdx.x; i < n2;
         i += gridDim.x * blockDim.x) {
        float2 v = src[i];
        __half2 h = __floats2half2_rn(v.x, v.y);
        float2 hb = __half22float2(h);
        __half2 l = __floats2half2_rn(v.x - hb.x, v.y - hb.y);
        hi[i] = h;
        lo[i] = l;
    }
}

struct WSplit { const float* src[8]; };

__global__ __launch_bounds__(256)
void split_w_kernel(WSplit ws)
{
    const int z = blockIdx.y;
    const float2* src = (const float2*)ws.src[z];
    __half2* hi = (__half2*)&g_W_h[z][0];
    __half2* lo = (__half2*)&g_W_l[z][0];
    const int n2 = DMODEL * DMODEL / 2;
    for (int i = blockIdx.x * blockDim.x + threadIdx.x; i < n2;
         i += gridDim.x * blockDim.x) {
        float2 v = src[i];
        __half2 h = __floats2half2_rn(v.x, v.y);
        float2 hb = __half22float2(h);
        __half2 l = __floats2half2_rn(v.x - hb.x, v.y - hb.y);
        hi[i] = h;
        lo[i] = l;
    }
}

// ---------------------------------------------------------------------------
// split-fp16 tensor-core GEMM: C = X @ W^T + bias
//   CTA 128x128, 8 warps (4m x 2n), warp tile 32x64, 3-stage cp.async,
//   register-double-buffered B fragments (LDSM latency hidden behind MMAs).
// ---------------------------------------------------------------------------
struct GemmBatch {
    const __half* Xh[6];
    const __half* Xl[6];
    const __half* Wh[6];
    const __half* Wl[6];
    const float*  bias[6];
    float*        C[6];
};

__global__ __launch_bounds__(256, 2)
void gemm_mma_kernel(GemmBatch args)
{
    const int z = blockIdx.z;
    const __half* __restrict__ Xh = args.Xh[z];
    const __half* __restrict__ Xl = args.Xl[z];
    const __half* __restrict__ Wh = args.Wh[z];
    const __half* __restrict__ Wl = args.Wl[z];
    const float*  __restrict__ bias = args.bias[z];
    float*        __restrict__ C    = args.C[z];

    const int n0 = blockIdx.x * BN;
    const int m0 = blockIdx.y * BM;

    extern __shared__ __align__(128) char smraw[];
    const uint32_t sbase = smem_u32(smraw);

    const int tid  = threadIdx.x;
    const int wid  = tid >> 5;
    const int lane = tid & 31;
    const int r  = lane >> 2;
    const int cq = lane & 3;

    const int wm = (wid >> 1) * 32;   // 0,32,64,96
    const int wn = (wid & 1) * 64;    // 0,64

    const int a_row_in16 = (lane & 7) + ((lane >> 3) & 1) * 8;
    const int a_kh       = lane >> 4;
    const int b_row_in16 = (lane & 7) + ((lane >> 4) & 1) * 8;
    const int b_kh       = (lane >> 3) & 1;

    float acc[2][8][4];
#pragma unroll
    for (int i = 0; i < 2; ++i)
#pragma unroll
        for (int j = 0; j < 8; ++j)
#pragma unroll
            for (int k = 0; k < 4; ++k)
                acc[i][j][k] = 0.f;

#define LOAD_STAGE(kt, s) do {                                                  \
        const uint32_t st = sbase + (s) * STAGE_BYTES;                          \
        const size_t koff = (size_t)(kt) * BK;                                  \
        _Pragma("unroll")                                                       \
        for (int j = 0; j < 4; ++j) {                                           \
            int idx = tid + j * 256; int row = idx >> 3; int c = idx & 7;       \
            const __half* src = (c < 4) ? Xh : Xl;                              \
            cp16(st + row * 128 + ((c ^ (row & 7)) << 4),                       \
                 src + (size_t)(m0 + row) * DMODEL + koff + (c & 3) * 8);       \
        }                                                                       \
        _Pragma("unroll")                                                       \
        for (int j = 0; j < 4; ++j) {                                           \
            int idx = tid + j * 256; int row = idx >> 3; int c = idx & 7;       \
            const __half* src = (c < 4) ? Wh : Wl;                              \
            cp16(st + 16384 + row * 128 + ((c ^ (row & 7)) << 4),               \
                 src + (size_t)(n0 + row) * DMODEL + koff + (c & 3) * 8);       \
        }                                                                       \
        CP_COMMIT();                                                            \
    } while (0)

// load B fragments (4 n-atoms) for (ksv, grpv) into buffer bu
#define LOAD_BFRAGS(bu, ksv, grpv) do {                                         \
        _Pragma("unroll")                                                       \
        for (int pair = 0; pair < 2; ++pair) {                                  \
            const int brow = wn + (grpv) * 32 + pair * 16 + b_row_in16;         \
            const int sw = brow & 7;                                            \
            const uint32_t rb = bB + brow * 128;                                \
            uint32_t th[4], tl[4];                                              \
            ldm_x4(th, rb + (((2 * (ksv) + b_kh) ^ sw) << 4));                  \
            ldm_x4(tl, rb + (((2 * (ksv) + b_kh + 4) ^ sw) << 4));              \
            bhb[bu][pair * 2 + 0][0] = th[0]; bhb[bu][pair * 2 + 0][1] = th[1]; \
            bhb[bu][pair * 2 + 1][0] = th[2]; bhb[bu][pair * 2 + 1][1] = th[3]; \
            blb[bu][pair * 2 + 0][0] = tl[0]; blb[bu][pair * 2 + 0][1] = tl[1]; \
            blb[bu][pair * 2 + 1][0] = tl[2]; blb[bu][pair * 2 + 1][1] = tl[3]; \
        }                                                                       \
    } while (0)

// MMA passes for one group using buffer bu (same-acc distance = 8)
#define MMA_GROUP(bu, grpv) do {                                                \
        _Pragma("unroll")                                                       \
        for (int i = 0; i < 4; ++i) {                                           \
            mma_f16(acc[0][(grpv) * 4 + i], ah[0], bhb[bu][i]);                 \
            mma_f16(acc[1][(grpv) * 4 + i], ah[1], bhb[bu][i]);                 \
        }                                                                       \
        _Pragma("unroll")                                                       \
        for (int i = 0; i < 4; ++i) {                                           \
            mma_f16(acc[0][(grpv) * 4 + i], ah[0], blb[bu][i]);                 \
            mma_f16(acc[1][(grpv) * 4 + i], ah[1], blb[bu][i]);                 \
        }                                                                       \
        _Pragma("unroll")                                                       \
        for (int i = 0; i < 4; ++i) {                                           \
            mma_f16(acc[0][(grpv) * 4 + i], al[0], bhb[bu][i]);                 \
            mma_f16(acc[1][(grpv) * 4 + i], al[1], bhb[bu][i]);                 \
        }                                                                       \
    } while (0)

#define LOAD_AFRAGS(ksv) do {                                                   \
        _Pragma("unroll")                                                       \
        for (int ma = 0; ma < 2; ++ma) {                                        \
            const int arow = wm + ma * 16 + a_row_in16;                         \
            const int sw = arow & 7;                                            \
            const uint32_t rb = aB + arow * 128;                                \
            ldm_x4(ah[ma], rb + (((2 * (ksv) + a_kh) ^ sw) << 4));              \
            ldm_x4(al[ma], rb + (((2 * (ksv) + a_kh + 4) ^ sw) << 4));          \
        }                                                                       \
    } while (0)

    LOAD_STAGE(0, 0);
    LOAD_STAGE(1, 1);

    uint32_t bhb[2][4][2], blb[2][4][2];   // double-buffered B fragments
    uint32_t ah[2][4], al[2][4];

    const int NKT = DMODEL / BK;   // 16
    for (int kt = 0; kt < NKT; ++kt) {
        cp_wait<1>();
        __syncthreads();
        if (kt + 2 < NKT) {
            LOAD_STAGE(kt + 2, (kt + 2) % 3);
        } else {
            CP_COMMIT();
        }

        const uint32_t aB = sbase + (kt % 3) * STAGE_BYTES;
        const uint32_t bB = aB + 16384;

        // ---- ks = 0 ----
        LOAD_AFRAGS(0);
        LOAD_BFRAGS(0, 0, 0);
        LOAD_BFRAGS(1, 0, 1);        // prefetch grp1 (covered by grp0 MMAs)
        MMA_GROUP(0, 0);
        LOAD_BFRAGS(0, 1, 0);        // prefetch ks1 grp0 (covered by grp1 MMAs)
        MMA_GROUP(1, 1);
        // ---- ks = 1 ----
        LOAD_AFRAGS(1);
        LOAD_BFRAGS(1, 1, 1);        // prefetch grp1 (covered by grp0 MMAs)
        MMA_GROUP(0, 0);
        MMA_GROUP(1, 1);
    }
#undef LOAD_STAGE
#undef LOAD_BFRAGS
#undef MMA_GROUP
#undef LOAD_AFRAGS

    // epilogue: acc[ma][j] -> n offset = (j>>2)*32 + (j&3)*8
#pragma unroll
    for (int j = 0; j < 8; ++j) {
        const int col = n0 + wn + (j >> 2) * 32 + (j & 3) * 8 + 2 * cq;
        const float2 bv = *(const float2*)(bias + col);
#pragma unroll
        for (int ma = 0; ma < 2; ++ma) {
            const int row = m0 + wm + ma * 16 + r;
            float2 v0, v1;
            v0.x = acc[ma][j][0] + bv.x;
            v0.y = acc[ma][j][1] + bv.y;
            v1.x = acc[ma][j][2] + bv.x;
            v1.y = acc[ma][j][3] + bv.y;
            *(float2*)(C + (size_t)row * DMODEL + col)       = v0;
            *(float2*)(C + (size_t)(row + 8) * DMODEL + col) = v1;
        }
    }
}

// ---------------------------------------------------------------------------
// Per-sample head-mixing attention; emits fp16 hi/lo directly. 8 warps/CTA.
// ---------------------------------------------------------------------------
#define AW 8
__global__ __launch_bounds__(32 * AW)
void attention_kernel(const float* __restrict__ q1, const float* __restrict__ k1,
                      const float* __restrict__ v1, const float* __restrict__ q2,
                      const float* __restrict__ k2, const float* __restrict__ v2,
                      __half* __restrict__ o1h, __half* __restrict__ o1l,
                      __half* __restrict__ o2h, __half* __restrict__ o2l)
{
    __shared__ float sq[AW][NHEADS][68];
    __shared__ float sk[AW][NHEADS][68];
    __shared__ float sv[AW][NHEADS][68];
    __shared__ float ss[AW][NHEADS][NHEADS];

    const int w = threadIdx.x >> 5;
    const int l = threadIdx.x & 31;
    const int s = blockIdx.x * AW + w;

    const float* Q[2] = { q1 + (size_t)s * DMODEL, q2 + (size_t)s * DMODEL };
    const float* K[2] = { k1 + (size_t)s * DMODEL, k2 + (size_t)s * DMODEL };
    const float* V[2] = { v1 + (size_t)s * DMODEL, v2 + (size_t)s * DMODEL };
    __half* OH[2] = { o1h + (size_t)s * DMODEL, o2h + (size_t)s * DMODEL };
    __half* OL[2] = { o1l + (size_t)s * DMODEL, o2l + (size_t)s * DMODEL };

    for (int side = 0; side < 2; ++side) {
        const float* q = Q[side];
        const float* k = K[side];
        const float* v = V[side];

#pragma unroll
        for (int i = 0; i < 16; ++i) {
            const int idx = i * 32 + l;
            const int h = idx >> 6, d = idx & 63;
            sq[w][h][d] = q[idx];
            sk[w][h][d] = k[idx];
            sv[w][h][d] = v[idx];
        }
        __syncwarp();

#pragma unroll
        for (int pp = 0; pp < 2; ++pp) {
            const int p = l + pp * 32;
            const int h = p >> 3, e = p & 7;
            float acc = 0.f;
#pragma unroll
            for (int d = 0; d < DHEAD; ++d)
                acc = fmaf(sq[w][h][d], sk[w][e][d], acc);
            ss[w][h][e] = acc * 0.125f;
        }
        __syncwarp();

        if (l < NHEADS) {
            float m = -1e30f;
#pragma unroll
            for (int e = 0; e < NHEADS; ++e) m = fmaxf(m, ss[w][l][e]);
            float ex[NHEADS];
            float sum = 0.f;
#pragma unroll
            for (int e = 0; e < NHEADS; ++e) { ex[e] = expf(ss[w][l][e] - m); sum += ex[e]; }
            const float inv = 1.f / sum;
#pragma unroll
            for (int e = 0; e < NHEADS; ++e) ss[w][l][e] = ex[e] * inv;
        }
        __syncwarp();

#pragma unroll
        for (int dd = 0; dd < 2; ++dd) {
            const int d = l + dd * 32;
#pragma unroll
            for (int h = 0; h < NHEADS; ++h) {
                float acc = 0.f;
#pragma unroll
                for (int e = 0; e < NHEADS; ++e)
                    acc = fmaf(ss[w][h][e], sv[w][e][d], acc);
                const __half hv = __float2half_rn(acc);
                const __half lv = __float2half_rn(acc - __half2float(hv));
                OH[side][h * DHEAD + d] = hv;
                OL[side][h * DHEAD + d] = lv;
            }
        }
        __syncwarp();
    }
}

// ---------------------------------------------------------------------------
// kernel_launch
// ---------------------------------------------------------------------------
extern "C" void kernel_launch(void* const* d_in, const int* in_sizes, int n_in,
                              void* d_out, int out_size)
{
    const float* prot = (const float*)d_in[0];
    const float* lig  = (const float*)d_in[1];
    const float* Wq1 = (const float*)d_in[2];  const float* bq1 = (const float*)d_in[3];
    const float* Wk1 = (const float*)d_in[4];  const float* bk1 = (const float*)d_in[5];
    const float* Wv1 = (const float*)d_in[6];  const float* bv1 = (const float*)d_in[7];
    const float* Wq2 = (const float*)d_in[8];  const float* bq2 = (const float*)d_in[9];
    const float* Wk2 = (const float*)d_in[10]; const float* bk2 = (const float*)d_in[11];
    const float* Wv2 = (const float*)d_in[12]; const float* bv2 = (const float*)d_in[13];
    const float* Wo1 = (const float*)d_in[14]; const float* bo1 = (const float*)d_in[15];
    const float* Wo2 = (const float*)d_in[16]; const float* bo2 = (const float*)d_in[17];

    float* out      = (float*)d_out;
    float* prot_out = out;
    float* lig_out  = out + (size_t)NB * DMODEL;

    float *q1, *k1, *v1, *q2, *k2, *v2;
    cudaGetSymbolAddress((void**)&q1, g_q1);
    cudaGetSymbolAddress((void**)&k1, g_k1);
    cudaGetSymbolAddress((void**)&v1, g_v1);
    cudaGetSymbolAddress((void**)&q2, g_q2);
    cudaGetSymbolAddress((void**)&k2, g_k2);
    cudaGetSymbolAddress((void**)&v2, g_v2);

    __half *ph, *pl, *lh, *ll, *o1h, *o1l, *o2h, *o2l, *wh, *wl;
    cudaGetSymbolAddress((void**)&ph,  g_prot_h);
    cudaGetSymbolAddress((void**)&pl,  g_prot_l);
    cudaGetSymbolAddress((void**)&lh,  g_lig_h);
    cudaGetSymbolAddress((void**)&ll,  g_lig_l);
    cudaGetSymbolAddress((void**)&o1h, g_o1_h);
    cudaGetSymbolAddress((void**)&o1l, g_o1_l);
    cudaGetSymbolAddress((void**)&o2h, g_o2_h);
    cudaGetSymbolAddress((void**)&o2l, g_o2_l);
    cudaGetSymbolAddress((void**)&wh,  g_W_h);
    cudaGetSymbolAddress((void**)&wl,  g_W_l);

    const int NE2 = NB * DMODEL / 2;

    SplitBatch sb;
    sb.src[0] = (const float2*)prot; sb.hi[0] = (__half2*)ph; sb.lo[0] = (__half2*)pl;
    sb.src[1] = (const float2*)lig;  sb.hi[1] = (__half2*)lh; sb.lo[1] = (__half2*)ll;
    split_kernel<<<dim3(2048, 2), 256>>>(sb, NE2);
    WSplit ws;
    ws.src[0] = Wq1; ws.src[1] = Wk1; ws.src[2] = Wv1; ws.src[3] = Wq2;
    ws.src[4] = Wk2; ws.src[5] = Wv2; ws.src[6] = Wo1; ws.src[7] = Wo2;
    split_w_kernel<<<dim3(64, 8), 256>>>(ws);

    const int DSM = NSTAGE * STAGE_BYTES;   // 98304
    cudaFuncSetAttribute(gemm_mma_kernel, cudaFuncAttributeMaxDynamicSharedMemorySize, DSM);

    const size_t WSZ = (size_t)DMODEL * DMODEL;
#define WH(i) (wh + (size_t)(i) * WSZ)
#define WL(i) (wl + (size_t)(i) * WSZ)

    GemmBatch pj;
    pj.Xh[0] = ph; pj.Xl[0] = pl; pj.Wh[0] = WH(0); pj.Wl[0] = WL(0); pj.bias[0] = bq1; pj.C[0] = q1;
    pj.Xh[1] = lh; pj.Xl[1] = ll; pj.Wh[1] = WH(1); pj.Wl[1] = WL(1); pj.bias[1] = bk1; pj.C[1] = k1;
    pj.Xh[2] = lh; pj.Xl[2] = ll; pj.Wh[2] = WH(2); pj.Wl[2] = WL(2); pj.bias[2] = bv1; pj.C[2] = v1;
    pj.Xh[3] = lh; pj.Xl[3] = ll; pj.Wh[3] = WH(3); pj.Wl[3] = WL(3); pj.bias[3] = bq2; pj.C[3] = q2;
    pj.Xh[4] = ph; pj.Xl[4] = pl; pj.Wh[4] = WH(4); pj.Wl[4] = WL(4); pj.bias[4] = bk2; pj.C[4] = k2;
    pj.Xh[5] = ph; pj.Xl[5] = pl; pj.Wh[5] = WH(5); pj.Wl[5] = WL(5); pj.bias[5] = bv2; pj.C[5] = v2;

    dim3 gproj(DMODEL / BN, NB / BM, 6);
    gemm_mma_kernel<<<gproj, 256, DSM>>>(pj);

    attention_kernel<<<NB / AW, 32 * AW>>>(q1, k1, v1, q2, k2, v2, o1h, o1l, o2h, o2l);

    GemmBatch op;
    op.Xh[0] = o1h; op.Xl[0] = o1l; op.Wh[0] = WH(6); op.Wl[0] = WL(6); op.bias[0] = bo1; op.C[0] = prot_out;
    op.Xh[1] = o2h; op.Xl[1] = o2l; op.Wh[1] = WH(7); op.Wl[1] = WL(7); op.bias[1] = bo2; op.C[1] = lig_out;
    for (int i = 2; i < 6; ++i) {
        op.Xh[i] = o1h; op.Xl[i] = o1l; op.Wh[i] = WH(6); op.Wl[i] = WL(6);
        op.bias[i] = bo1; op.C[i] = prot_out;
    }

    dim3 gout(DMODEL / BN, NB / BM, 2);
    gemm_mma_kernel<<<gout, 256, DSM>>>(op);
#undef WH
#undef WL
}

// round 8
// speedup vs baseline: 3.1435x; 1.3080x over previous
#include <cuda_runtime.h>
#include <cuda_fp16.h>
#include <cstdint>
#include <math.h>

#define NB     32768
#define DMODEL 512
#define NHEADS 8
#define DHEAD  64

// GEMM tiling
#define BM 128
#define BN 128
#define BK 32                 // K halves per stage
#define NSTAGE 3
#define STAGE_BYTES 32768     // A 16KB + B 16KB (128 rows x 128B each)

// ---------------------------------------------------------------------------
// Scratch buffers
// ---------------------------------------------------------------------------
__device__ float g_q1[(size_t)NB * DMODEL];
__device__ float g_k1[(size_t)NB * DMODEL];
__device__ float g_v1[(size_t)NB * DMODEL];
__device__ float g_q2[(size_t)NB * DMODEL];
__device__ float g_k2[(size_t)NB * DMODEL];
__device__ float g_v2[(size_t)NB * DMODEL];

__device__ __half g_prot_h[(size_t)NB * DMODEL];
__device__ __half g_prot_l[(size_t)NB * DMODEL];
__device__ __half g_lig_h [(size_t)NB * DMODEL];
__device__ __half g_lig_l [(size_t)NB * DMODEL];
__device__ __half g_o1_h  [(size_t)NB * DMODEL];
__device__ __half g_o1_l  [(size_t)NB * DMODEL];
__device__ __half g_o2_h  [(size_t)NB * DMODEL];
__device__ __half g_o2_l  [(size_t)NB * DMODEL];
__device__ __half g_W_h[8][DMODEL * DMODEL];
__device__ __half g_W_l[8][DMODEL * DMODEL];

// ---------------------------------------------------------------------------
// helpers
// ---------------------------------------------------------------------------
__device__ __forceinline__ uint32_t smem_u32(const void* p) {
    uint32_t a;
    asm("{ .reg .u64 t; cvta.to.shared.u64 t, %1; cvt.u32.u64 %0, t; }"
        : "=r"(a) : "l"(p));
    return a;
}
__device__ __forceinline__ void cp16(uint32_t dst, const void* src) {
    asm volatile("cp.async.cg.shared.global [%0], [%1], 16;" :: "r"(dst), "l"(src));
}
#define CP_COMMIT() asm volatile("cp.async.commit_group;" ::: "memory")
template <int N> __device__ __forceinline__ void cp_wait() {
    asm volatile("cp.async.wait_group %0;" :: "n"(N) : "memory");
}

__device__ __forceinline__ void ldm_x4(uint32_t* d, uint32_t addr) {
    asm volatile("ldmatrix.sync.aligned.m8n8.x4.shared.b16 {%0,%1,%2,%3}, [%4];"
                 : "=r"(d[0]), "=r"(d[1]), "=r"(d[2]), "=r"(d[3]) : "r"(addr));
}

__device__ __forceinline__ void mma_f16(float* d, const uint32_t* a, const uint32_t* b) {
    asm volatile(
        "mma.sync.aligned.m16n8k16.row.col.f32.f16.f16.f32 "
        "{%0,%1,%2,%3}, {%4,%5,%6,%7}, {%8,%9}, {%0,%1,%2,%3};"
        : "+f"(d[0]), "+f"(d[1]), "+f"(d[2]), "+f"(d[3])
        : "r"(a[0]), "r"(a[1]), "r"(a[2]), "r"(a[3]), "r"(b[0]), "r"(b[1]));
}

// ---------------------------------------------------------------------------
// fp32 -> (hi fp16, lo fp16) split kernels
// ---------------------------------------------------------------------------
struct SplitBatch {
    const float2* src[2];
    __half2* hi[2];
    __half2* lo[2];
};

__global__ __launch_bounds__(256)
void split_kernel(SplitBatch sb, int n2)
{
    const int z = blockIdx.y;
    const float2* __restrict__ src = sb.src[z];
    __half2* __restrict__ hi = sb.hi[z];
    __half2* __restrict__ lo = sb.lo[z];
    for (int i = blockIdx.x * blockDim.x + threadIdx.x; i < n2;
         i += gridDim.x * blockDim.x) {
        float2 v = src[i];
        __half2 h = __floats2half2_rn(v.x, v.y);
        float2 hb = __half22float2(h);
        __half2 l = __floats2half2_rn(v.x - hb.x, v.y - hb.y);
        hi[i] = h;
        lo[i] = l;
    }
}

struct WSplit { const float* src[8]; };

__global__ __launch_bounds__(256)
void split_w_kernel(WSplit ws)
{
    const int z = blockIdx.y;
    const float2* src = (const float2*)ws.src[z];
    __half2* hi = (__half2*)&g_W_h[z][0];
    __half2* lo = (__half2*)&g_W_l[z][0];
    const int n2 = DMODEL * DMODEL / 2;
    for (int i = blockIdx.x * blockDim.x + threadIdx.x; i < n2;
         i += gridDim.x * blockDim.x) {
        float2 v = src[i];
        __half2 h = __floats2half2_rn(v.x, v.y);
        float2 hb = __half22float2(h);
        __half2 l = __floats2half2_rn(v.x - hb.x, v.y - hb.y);
        hi[i] = h;
        lo[i] = l;
    }
}

// ---------------------------------------------------------------------------
// split-fp16 tensor-core GEMM (unchanged from R7 best)
// ---------------------------------------------------------------------------
struct GemmBatch {
    const __half* Xh[6];
    const __half* Xl[6];
    const __half* Wh[6];
    const __half* Wl[6];
    const float*  bias[6];
    float*        C[6];
};

__global__ __launch_bounds__(256, 2)
void gemm_mma_kernel(GemmBatch args)
{
    const int z = blockIdx.z;
    const __half* __restrict__ Xh = args.Xh[z];
    const __half* __restrict__ Xl = args.Xl[z];
    const __half* __restrict__ Wh = args.Wh[z];
    const __half* __restrict__ Wl = args.Wl[z];
    const float*  __restrict__ bias = args.bias[z];
    float*        __restrict__ C    = args.C[z];

    const int n0 = blockIdx.x * BN;
    const int m0 = blockIdx.y * BM;

    extern __shared__ __align__(128) char smraw[];
    const uint32_t sbase = smem_u32(smraw);

    const int tid  = threadIdx.x;
    const int wid  = tid >> 5;
    const int lane = tid & 31;
    const int r  = lane >> 2;
    const int cq = lane & 3;

    const int wm = (wid >> 1) * 32;
    const int wn = (wid & 1) * 64;

    const int a_row_in16 = (lane & 7) + ((lane >> 3) & 1) * 8;
    const int a_kh       = lane >> 4;
    const int b_row_in16 = (lane & 7) + ((lane >> 4) & 1) * 8;
    const int b_kh       = (lane >> 3) & 1;

    float acc[2][8][4];
#pragma unroll
    for (int i = 0; i < 2; ++i)
#pragma unroll
        for (int j = 0; j < 8; ++j)
#pragma unroll
            for (int k = 0; k < 4; ++k)
                acc[i][j][k] = 0.f;

#define LOAD_STAGE(kt, s) do {                                                  \
        const uint32_t st = sbase + (s) * STAGE_BYTES;                          \
        const size_t koff = (size_t)(kt) * BK;                                  \
        _Pragma("unroll")                                                       \
        for (int j = 0; j < 4; ++j) {                                           \
            int idx = tid + j * 256; int row = idx >> 3; int c = idx & 7;       \
            const __half* src = (c < 4) ? Xh : Xl;                              \
            cp16(st + row * 128 + ((c ^ (row & 7)) << 4),                       \
                 src + (size_t)(m0 + row) * DMODEL + koff + (c & 3) * 8);       \
        }                                                                       \
        _Pragma("unroll")                                                       \
        for (int j = 0; j < 4; ++j) {                                           \
            int idx = tid + j * 256; int row = idx >> 3; int c = idx & 7;       \
            const __half* src = (c < 4) ? Wh : Wl;                              \
            cp16(st + 16384 + row * 128 + ((c ^ (row & 7)) << 4),               \
                 src + (size_t)(n0 + row) * DMODEL + koff + (c & 3) * 8);       \
        }                                                                       \
        CP_COMMIT();                                                            \
    } while (0)

#define LOAD_BFRAGS(bu, ksv, grpv) do {                                         \
        _Pragma("unroll")                                                       \
        for (int pair = 0; pair < 2; ++pair) {                                  \
            const int brow = wn + (grpv) * 32 + pair * 16 + b_row_in16;         \
            const int sw = brow & 7;                                            \
            const uint32_t rb = bB + brow * 128;                                \
            uint32_t th[4], tl[4];                                              \
            ldm_x4(th, rb + (((2 * (ksv) + b_kh) ^ sw) << 4));                  \
            ldm_x4(tl, rb + (((2 * (ksv) + b_kh + 4) ^ sw) << 4));              \
            bhb[bu][pair * 2 + 0][0] = th[0]; bhb[bu][pair * 2 + 0][1] = th[1]; \
            bhb[bu][pair * 2 + 1][0] = th[2]; bhb[bu][pair * 2 + 1][1] = th[3]; \
            blb[bu][pair * 2 + 0][0] = tl[0]; blb[bu][pair * 2 + 0][1] = tl[1]; \
            blb[bu][pair * 2 + 1][0] = tl[2]; blb[bu][pair * 2 + 1][1] = tl[3]; \
        }                                                                       \
    } while (0)

#define MMA_GROUP(bu, grpv) do {                                                \
        _Pragma("unroll")                                                       \
        for (int i = 0; i < 4; ++i) {                                           \
            mma_f16(acc[0][(grpv) * 4 + i], ah[0], bhb[bu][i]);                 \
            mma_f16(acc[1][(grpv) * 4 + i], ah[1], bhb[bu][i]);                 \
        }                                                                       \
        _Pragma("unroll")                                                       \
        for (int i = 0; i < 4; ++i) {                                           \
            mma_f16(acc[0][(grpv) * 4 + i], ah[0], blb[bu][i]);                 \
            mma_f16(acc[1][(grpv) * 4 + i], ah[1], blb[bu][i]);                 \
        }                                                                       \
        _Pragma("unroll")                                                       \
        for (int i = 0; i < 4; ++i) {                                           \
            mma_f16(acc[0][(grpv) * 4 + i], al[0], bhb[bu][i]);                 \
            mma_f16(acc[1][(grpv) * 4 + i], al[1], bhb[bu][i]);                 \
        }                                                                       \
    } while (0)

#define LOAD_AFRAGS(ksv) do {                                                   \
        _Pragma("unroll")                                                       \
        for (int ma = 0; ma < 2; ++ma) {                                        \
            const int arow = wm + ma * 16 + a_row_in16;                         \
            const int sw = arow & 7;                                            \
            const uint32_t rb = aB + arow * 128;                                \
            ldm_x4(ah[ma], rb + (((2 * (ksv) + a_kh) ^ sw) << 4));              \
            ldm_x4(al[ma], rb + (((2 * (ksv) + a_kh + 4) ^ sw) << 4));          \
        }                                                                       \
    } while (0)

    LOAD_STAGE(0, 0);
    LOAD_STAGE(1, 1);

    uint32_t bhb[2][4][2], blb[2][4][2];
    uint32_t ah[2][4], al[2][4];

    const int NKT = DMODEL / BK;
    for (int kt = 0; kt < NKT; ++kt) {
        cp_wait<1>();
        __syncthreads();
        if (kt + 2 < NKT) {
            LOAD_STAGE(kt + 2, (kt + 2) % 3);
        } else {
            CP_COMMIT();
        }

        const uint32_t aB = sbase + (kt % 3) * STAGE_BYTES;
        const uint32_t bB = aB + 16384;

        LOAD_AFRAGS(0);
        LOAD_BFRAGS(0, 0, 0);
        LOAD_BFRAGS(1, 0, 1);
        MMA_GROUP(0, 0);
        LOAD_BFRAGS(0, 1, 0);
        MMA_GROUP(1, 1);
        LOAD_AFRAGS(1);
        LOAD_BFRAGS(1, 1, 1);
        MMA_GROUP(0, 0);
        MMA_GROUP(1, 1);
    }
#undef LOAD_STAGE
#undef LOAD_BFRAGS
#undef MMA_GROUP
#undef LOAD_AFRAGS

#pragma unroll
    for (int j = 0; j < 8; ++j) {
        const int col = n0 + wn + (j >> 2) * 32 + (j & 3) * 8 + 2 * cq;
        const float2 bv = *(const float2*)(bias + col);
#pragma unroll
        for (int ma = 0; ma < 2; ++ma) {
            const int row = m0 + wm + ma * 16 + r;
            float2 v0, v1;
            v0.x = acc[ma][j][0] + bv.x;
            v0.y = acc[ma][j][1] + bv.y;
            v1.x = acc[ma][j][2] + bv.x;
            v1.y = acc[ma][j][3] + bv.y;
            *(float2*)(C + (size_t)row * DMODEL + col)       = v0;
            *(float2*)(C + (size_t)(row + 8) * DMODEL + col) = v1;
        }
    }
}

// ---------------------------------------------------------------------------
// Attention: one warp per sample. float4 loads, shuffle softmax,
// smem-staged coalesced half2 hi/lo stores.
// ---------------------------------------------------------------------------
#define AW 8
__global__ __launch_bounds__(32 * AW)
void attention_kernel(const float* __restrict__ q1, const float* __restrict__ k1,
                      const float* __restrict__ v1, const float* __restrict__ q2,
                      const float* __restrict__ k2, const float* __restrict__ v2,
                      __half* __restrict__ o1h, __half* __restrict__ o1l,
                      __half* __restrict__ o2h, __half* __restrict__ o2l)
{
    // [w][h][68]: 68-stride keeps float4 alignment (272B, 16-aligned)
    __shared__ float sq[AW][NHEADS][68];
    __shared__ float sk[AW][NHEADS][68];
    __shared__ float sv[AW][NHEADS][68];
    __shared__ float ss[AW][NHEADS][NHEADS];

    const int w = threadIdx.x >> 5;
    const int l = threadIdx.x & 31;
    const int s = blockIdx.x * AW + w;

    const float* Q[2] = { q1 + (size_t)s * DMODEL, q2 + (size_t)s * DMODEL };
    const float* K[2] = { k1 + (size_t)s * DMODEL, k2 + (size_t)s * DMODEL };
    const float* V[2] = { v1 + (size_t)s * DMODEL, v2 + (size_t)s * DMODEL };
    __half* OH[2] = { o1h + (size_t)s * DMODEL, o2h + (size_t)s * DMODEL };
    __half* OL[2] = { o1l + (size_t)s * DMODEL, o2l + (size_t)s * DMODEL };

    const int h0 = l >> 3;          // 0..3
    const int e0 = l & 7;           // 0..7

    for (int side = 0; side < 2; ++side) {
        const float4* q4 = (const float4*)Q[side];
        const float4* k4 = (const float4*)K[side];
        const float4* v4 = (const float4*)V[side];

        // ---- stage q,k,v via float4 (12 LDG.128 per lane, high MLP) ----
        float4 tq[4], tk[4], tv[4];
#pragma unroll
        for (int i = 0; i < 4; ++i) {
            const int idx = i * 32 + l;        // 0..127 float4s
            tq[i] = q4[idx];
            tk[i] = k4[idx];
            tv[i] = v4[idx];
        }
#pragma unroll
        for (int i = 0; i < 4; ++i) {
            const int idx = i * 32 + l;
            const int h = idx >> 4;            // 16 float4 per head
            const int d = (idx & 15) * 4;
            *(float4*)&sq[w][h][d] = tq[i];
            *(float4*)&sk[w][h][d] = tk[i];
            *(float4*)&sv[w][h][d] = tv[i];
        }
        __syncwarp();

        // ---- scores: lane handles (h0,e0) and (h0+4,e0), float4 dots ----
        float s0 = 0.f, s1 = 0.f;
#pragma unroll
        for (int d4 = 0; d4 < 16; ++d4) {
            const float4 kk = *(const float4*)&sk[w][e0][d4 * 4];
            const float4 qa = *(const float4*)&sq[w][h0][d4 * 4];
            const float4 qb = *(const float4*)&sq[w][h0 + 4][d4 * 4];
            s0 = fmaf(qa.x, kk.x, s0); s0 = fmaf(qa.y, kk.y, s0);
            s0 = fmaf(qa.z, kk.z, s0); s0 = fmaf(qa.w, kk.w, s0);
            s1 = fmaf(qb.x, kk.x, s1); s1 = fmaf(qb.y, kk.y, s1);
            s1 = fmaf(qb.z, kk.z, s1); s1 = fmaf(qb.w, kk.w, s1);
        }
        s0 *= 0.125f;
        s1 *= 0.125f;

        // ---- softmax over e via butterfly shuffles within 8-lane clusters ----
        float m0 = s0, m1 = s1;
#pragma unroll
        for (int d = 1; d < 8; d <<= 1) {
            m0 = fmaxf(m0, __shfl_xor_sync(0xFFFFFFFF, m0, d));
            m1 = fmaxf(m1, __shfl_xor_sync(0xFFFFFFFF, m1, d));
        }
        float x0 = expf(s0 - m0), x1 = expf(s1 - m1);
        float sum0 = x0, sum1 = x1;
#pragma unroll
        for (int d = 1; d < 8; d <<= 1) {
            sum0 += __shfl_xor_sync(0xFFFFFFFF, sum0, d);
            sum1 += __shfl_xor_sync(0xFFFFFFFF, sum1, d);
        }
        ss[w][h0][e0]     = x0 / sum0;
        ss[w][h0 + 4][e0] = x1 / sum1;
        __syncwarp();

        // ---- out[h][d] = sum_e a[h][e] v[e][d]; stage fp32 into sq ----
#pragma unroll
        for (int dd = 0; dd < 2; ++dd) {
            const int d = l + dd * 32;
#pragma unroll
            for (int h = 0; h < NHEADS; ++h) {
                float a = 0.f;
#pragma unroll
                for (int e = 0; e < NHEADS; ++e)
                    a = fmaf(ss[w][h][e], sv[w][e][d], a);
                sq[w][h][d] = a;
            }
        }
        __syncwarp();

        // ---- coalesced half2 hi/lo stores (8 x 4B per lane per buffer) ----
        __half2* oh2 = (__half2*)OH[side];
        __half2* ol2 = (__half2*)OL[side];
#pragma unroll
        for (int i = 0; i < 8; ++i) {
            const int j = i * 32 + l;          // 0..255 half2 pairs
            const int h = j >> 5;              // 32 pairs per head
            const int d = (j & 31) * 2;
            const float a = sq[w][h][d];
            const float b = sq[w][h][d + 1];
            const __half2 hv = __floats2half2_rn(a, b);
            const float2 hf = __half22float2(hv);
            const __half2 lv = __floats2half2_rn(a - hf.x, b - hf.y);
            oh2[j] = hv;
            ol2[j] = lv;
        }
        __syncwarp();
    }
}

// ---------------------------------------------------------------------------
// kernel_launch
// ---------------------------------------------------------------------------
extern "C" void kernel_launch(void* const* d_in, const int* in_sizes, int n_in,
                              void* d_out, int out_size)
{
    const float* prot = (const float*)d_in[0];
    const float* lig  = (const float*)d_in[1];
    const float* Wq1 = (const float*)d_in[2];  const float* bq1 = (const float*)d_in[3];
    const float* Wk1 = (const float*)d_in[4];  const float* bk1 = (const float*)d_in[5];
    const float* Wv1 = (const float*)d_in[6];  const float* bv1 = (const float*)d_in[7];
    const float* Wq2 = (const float*)d_in[8];  const float* bq2 = (const float*)d_in[9];
    const float* Wk2 = (const float*)d_in[10]; const float* bk2 = (const float*)d_in[11];
    const float* Wv2 = (const float*)d_in[12]; const float* bv2 = (const float*)d_in[13];
    const float* Wo1 = (const float*)d_in[14]; const float* bo1 = (const float*)d_in[15];
    const float* Wo2 = (const float*)d_in[16]; const float* bo2 = (const float*)d_in[17];

    float* out      = (float*)d_out;
    float* prot_out = out;
    float* lig_out  = out + (size_t)NB * DMODEL;

    float *q1, *k1, *v1, *q2, *k2, *v2;
    cudaGetSymbolAddress((void**)&q1, g_q1);
    cudaGetSymbolAddress((void**)&k1, g_k1);
    cudaGetSymbolAddress((void**)&v1, g_v1);
    cudaGetSymbolAddress((void**)&q2, g_q2);
    cudaGetSymbolAddress((void**)&k2, g_k2);
    cudaGetSymbolAddress((void**)&v2, g_v2);

    __half *ph, *pl, *lh, *ll, *o1h, *o1l, *o2h, *o2l, *wh, *wl;
    cudaGetSymbolAddress((void**)&ph,  g_prot_h);
    cudaGetSymbolAddress((void**)&pl,  g_prot_l);
    cudaGetSymbolAddress((void**)&lh,  g_lig_h);
    cudaGetSymbolAddress((void**)&ll,  g_lig_l);
    cudaGetSymbolAddress((void**)&o1h, g_o1_h);
    cudaGetSymbolAddress((void**)&o1l, g_o1_l);
    cudaGetSymbolAddress((void**)&o2h, g_o2_h);
    cudaGetSymbolAddress((void**)&o2l, g_o2_l);
    cudaGetSymbolAddress((void**)&wh,  g_W_h);
    cudaGetSymbolAddress((void**)&wl,  g_W_l);

    const int NE2 = NB * DMODEL / 2;

    SplitBatch sb;
    sb.src[0] = (const float2*)prot; sb.hi[0] = (__half2*)ph; sb.lo[0] = (__half2*)pl;
    sb.src[1] = (const float2*)lig;  sb.hi[1] = (__half2*)lh; sb.lo[1] = (__half2*)ll;
    split_kernel<<<dim3(2048, 2), 256>>>(sb, NE2);
    WSplit ws;
    ws.src[0] = Wq1; ws.src[1] = Wk1; ws.src[2] = Wv1; ws.src[3] = Wq2;
    ws.src[4] = Wk2; ws.src[5] = Wv2; ws.src[6] = Wo1; ws.src[7] = Wo2;
    split_w_kernel<<<dim3(64, 8), 256>>>(ws);

    const int DSM = NSTAGE * STAGE_BYTES;
    cudaFuncSetAttribute(gemm_mma_kernel, cudaFuncAttributeMaxDynamicSharedMemorySize, DSM);

    const size_t WSZ = (size_t)DMODEL * DMODEL;
#define WH(i) (wh + (size_t)(i) * WSZ)
#define WL(i) (wl + (size_t)(i) * WSZ)

    GemmBatch pj;
    pj.Xh[0] = ph; pj.Xl[0] = pl; pj.Wh[0] = WH(0); pj.Wl[0] = WL(0); pj.bias[0] = bq1; pj.C[0] = q1;
    pj.Xh[1] = lh; pj.Xl[1] = ll; pj.Wh[1] = WH(1); pj.Wl[1] = WL(1); pj.bias[1] = bk1; pj.C[1] = k1;
    pj.Xh[2] = lh; pj.Xl[2] = ll; pj.Wh[2] = WH(2); pj.Wl[2] = WL(2); pj.bias[2] = bv1; pj.C[2] = v1;
    pj.Xh[3] = lh; pj.Xl[3] = ll; pj.Wh[3] = WH(3); pj.Wl[3] = WL(3); pj.bias[3] = bq2; pj.C[3] = q2;
    pj.Xh[4] = ph; pj.Xl[4] = pl; pj.Wh[4] = WH(4); pj.Wl[4] = WL(4); pj.bias[4] = bk2; pj.C[4] = k2;
    pj.Xh[5] = ph; pj.Xl[5] = pl; pj.Wh[5] = WH(5); pj.Wl[5] = WL(5); pj.bias[5] = bv2; pj.C[5] = v2;

    dim3 gproj(DMODEL / BN, NB / BM, 6);
    gemm_mma_kernel<<<gproj, 256, DSM>>>(pj);

    attention_kernel<<<NB / AW, 32 * AW>>>(q1, k1, v1, q2, k2, v2, o1h, o1l, o2h, o2l);

    GemmBatch op;
    op.Xh[0] = o1h; op.Xl[0] = o1l; op.Wh[0] = WH(6); op.Wl[0] = WL(6); op.bias[0] = bo1; op.C[0] = prot_out;
    op.Xh[1] = o2h; op.Xl[1] = o2l; op.Wh[1] = WH(7); op.Wl[1] = WL(7); op.bias[1] = bo2; op.C[1] = lig_out;
    for (int i = 2; i < 6; ++i) {
        op.Xh[i] = o1h; op.Xl[i] = o1l; op.Wh[i] = WH(6); op.Wl[i] = WL(6);
        op.bias[i] = bo1; op.C[i] = prot_out;
    }

    dim3 gout(DMODEL / BN, NB / BM, 2);
    gemm_mma_kernel<<<gout, 256, DSM>>>(op);
#undef WH
#undef WL
}